// round 15
// baseline (speedup 1.0000x reference)
#include <cuda_runtime.h>
#include <cuda_bf16.h>
#include <math.h>
#include <stdint.h>

#define BATCH 2
#define H0 480
#define W0 640
#define NP0 (H0*W0)

#define PLANE 403200
#define OFF_S4 0
#define OFF_S2 19200
#define OFF_S1 96000

// ---------------- scratch (device globals) ----------------
__device__ float g_x   [BATCH*6 *PLANE];
__device__ float g_A   [BATCH*24*PLANE];
__device__ float g_csk [BATCH*9 *PLANE];
__device__ float g_curv[BATCH*3 *PLANE];
__device__ float g_D   [BATCH*NP0];
__device__ float g_D2  [BATCH*NP0];
__device__ float g_Dp  [BATCH*NP0];

// activations NHWC bf16 pair-planes: u32 = (bf16 ch c | bf16 ch c+1 << 16), 32 pairs
__device__ __align__(16) unsigned g_fh0[BATCH*NP0*32];
__device__ __align__(16) unsigned g_fl0[BATCH*NP0*32];
__device__ __align__(16) unsigned g_fh1[BATCH*NP0*32];
__device__ __align__(16) unsigned g_fl1[BATCH*NP0*32];

// enc0 scalar weights [ci][tap][co]
__device__ float g_wT0[6*9*64];
// mma weights prepacked [tap][co][ci pad 72] bf16 (hi / lo), 36 u32 per row
__device__ __align__(16) unsigned g_WH1[9*64*36];
__device__ __align__(16) unsigned g_WL1[9*64*36];
__device__ __align__(16) unsigned g_WH2[9*64*36];
__device__ __align__(16) unsigned g_WL2[9*64*36];
__device__ __align__(16) unsigned g_WHa[9*32*36];
__device__ __align__(16) unsigned g_WLa[9*32*36];
__device__ float g_bagc[32];

// ---------------- helpers ----------------
__device__ __forceinline__ uint32_t smem_u32(const void* p) {
    uint32_t a;
    asm("{ .reg .u64 t; cvta.to.shared.u64 t, %1; cvt.u32.u64 %0, t; }" : "=r"(a) : "l"(p));
    return a;
}
__device__ __forceinline__ void fma2(unsigned long long& d, unsigned long long a, unsigned long long b) {
    asm("fma.rn.f32x2 %0, %1, %2, %0;" : "+l"(d) : "l"(a), "l"(b));
}
__device__ __forceinline__ unsigned long long pack2(float lo, float hi) {
    unsigned long long r;
    asm("mov.b64 %0, {%1, %2};" : "=l"(r) : "f"(lo), "f"(hi));
    return r;
}
__device__ __forceinline__ void unpack2(unsigned long long v, float& lo, float& hi) {
    asm("mov.b64 {%0, %1}, %2;" : "=f"(lo), "=f"(hi) : "l"(v));
}
__device__ __forceinline__ void bfsplit(float v, unsigned short& h, unsigned short& l) {
    __nv_bfloat16 bh = __float2bfloat16_rn(v);
    float r = v - __bfloat162float(bh);
    __nv_bfloat16 bl = __float2bfloat16_rn(r);
    h = __bfloat16_as_ushort(bh);
    l = __bfloat16_as_ushort(bl);
}
__device__ __forceinline__ void mma16816(float& c0, float& c1, float& c2, float& c3,
                                         unsigned a0, unsigned a1, unsigned a2, unsigned a3,
                                         unsigned b0, unsigned b1) {
    asm volatile("mma.sync.aligned.m16n8k16.row.col.f32.bf16.bf16.f32 "
        "{%0,%1,%2,%3}, {%4,%5,%6,%7}, {%8,%9}, {%0,%1,%2,%3};"
        : "+f"(c0), "+f"(c1), "+f"(c2), "+f"(c3)
        : "r"(a0), "r"(a1), "r"(a2), "r"(a3), "r"(b0), "r"(b1));
}
__device__ __forceinline__ void ldsm_x4(unsigned& r0, unsigned& r1, unsigned& r2, unsigned& r3,
                                        unsigned addr) {
    asm volatile("ldmatrix.sync.aligned.m8n8.x4.shared.b16 {%0,%1,%2,%3}, [%4];"
        : "=r"(r0), "=r"(r1), "=r"(r2), "=r"(r3) : "r"(addr));
}

// ---------------- weight prep ----------------
__global__ void prep_weights(const float* __restrict__ w0,
                             const float* __restrict__ w1, const float* __restrict__ w2,
                             const float* __restrict__ wa, const float* __restrict__ ba,
                             const float* __restrict__ wg, const float* __restrict__ bg,
                             const float* __restrict__ wc, const float* __restrict__ bc) {
    int i = blockIdx.x*blockDim.x + threadIdx.x;
    if (i < 32) {
        float bv = 0.f;
        if (i < 24) bv = ba[i];
        else if (i < 27) bv = bg[i-24];
        else if (i < 30) bv = bc[i-27];
        g_bagc[i] = bv;
    }
    if (i < 3456) {                                  // enc0 OIHW -> [ci][t][co]
        int co = i / 54, r = i % 54, ci = r / 9, t = r % 9;
        g_wT0[(ci*9 + t)*64 + co] = w0[i];
    } else if (i < 40320) {                          // enc1: [tap][co][ci72]
        int j = i - 3456;
        int t = j / 4096, rem = j % 4096, co = rem / 64, ci = rem % 64;
        float v = w1[((size_t)co*64 + ci)*9 + t];
        unsigned short h, l; bfsplit(v, h, l);
        int idx = (t*64 + co)*72 + ci;
        ((unsigned short*)g_WH1)[idx] = h;
        ((unsigned short*)g_WL1)[idx] = l;
    } else if (i < 77184) {                          // enc2
        int j = i - 40320;
        int t = j / 4096, rem = j % 4096, co = rem / 64, ci = rem % 64;
        float v = w2[((size_t)co*64 + ci)*9 + t];
        unsigned short h, l; bfsplit(v, h, l);
        int idx = (t*64 + co)*72 + ci;
        ((unsigned short*)g_WH2)[idx] = h;
        ((unsigned short*)g_WL2)[idx] = l;
    } else if (i < 77184 + 18432) {                  // agc: 32 co
        int j = i - 77184;
        int t = j / 2048, rem = j % 2048, co = rem / 64, ci = rem % 64;
        float v = 0.f;
        if (co < 24)      v = wa[((size_t)co*64 + ci)*9 + t];
        else if (co < 27) v = wg[((size_t)(co-24)*64 + ci)*9 + t];
        else if (co < 30) v = wc[((size_t)(co-27)*65 + ci)*9 + t];
        unsigned short h, l; bfsplit(v, h, l);
        int idx = (t*32 + co)*72 + ci;
        ((unsigned short*)g_WHa)[idx] = h;
        ((unsigned short*)g_WLa)[idx] = l;
    }
}

// ---------------- antialiased downsample weights ----------------
template<int F>
__device__ __forceinline__ void down_weights(int i, int n, int& j0, float* w, float& ws) {
    float c = (float)(F*i) + 0.5f*(float)F - 0.5f;
    j0 = (int)ceilf(c - (float)F);
    ws = 0.f;
#pragma unroll
    for (int t = 0; t < 2*F; t++) {
        int j = j0 + t;
        float wv = (j >= 0 && j < n) ? (1.f - fabsf((float)j - c) * (1.f/(float)F)) : 0.f;
        w[t] = wv; ws += wv;
    }
}

// ---------------- per-scale input prep ----------------
template<int S, bool FIRST>
__global__ void prep_kernel(const float* __restrict__ I, const float* __restrict__ DL,
                            const float* __restrict__ ML, const float* __restrict__ E,
                            int off, int Hs, int Ws) {
    int NPs = Hs*Ws;
    int gid = blockIdx.x*blockDim.x + threadIdx.x;
    if (gid >= BATCH*NPs) return;
    int b = gid / NPs, p = gid % NPs;
    int y = p / Ws, x = p % Ws;

    float iv0, iv1, iv2, ev;
    if (S == 1) {
        const float* Ib = I + (size_t)b*3*NP0;
        iv0 = Ib[p]; iv1 = Ib[NP0 + p]; iv2 = Ib[2*NP0 + p];
        ev  = E[(size_t)b*NP0 + p];
    } else {
        float wy[2*S], wx[2*S], wys, wxs;
        int jy0, jx0;
        down_weights<S>(y, H0, jy0, wy, wys);
        down_weights<S>(x, W0, jx0, wx, wxs);
        float a0=0.f, a1=0.f, a2=0.f, ae=0.f;
        const float* Ib = I + (size_t)b*3*NP0;
        const float* Eb = E + (size_t)b*NP0;
#pragma unroll
        for (int ty = 0; ty < 2*S; ty++) {
            int yy = jy0 + ty;
            if (yy < 0 || yy >= H0) continue;
            float wyv = wy[ty];
#pragma unroll
            for (int tx = 0; tx < 2*S; tx++) {
                int xx = jx0 + tx;
                if (xx < 0 || xx >= W0) continue;
                float wv = wyv * wx[tx];
                int q = yy*W0 + xx;
                a0 += wv*Ib[q]; a1 += wv*Ib[NP0 + q]; a2 += wv*Ib[2*NP0 + q]; ae += wv*Eb[q];
            }
        }
        float inv = 1.f / (wys * wxs);
        iv0 = a0*inv; iv1 = a1*inv; iv2 = a2*inv; ev = ae*inv;
    }
    ev = fminf(fmaxf(ev, 0.f), 1.f);

    float dls, mls;
    if (S == 1) {
        mls = ML[(size_t)b*NP0 + p] > 0.f ? 1.f : 0.f;
        dls = DL[(size_t)b*NP0 + p];
    } else {
        float s = 0.f, c = 0.f;
        for (int dy = 0; dy < S; dy++)
            for (int dx = 0; dx < S; dx++) {
                int q = (y*S + dy)*W0 + (x*S + dx);
                float m = ML[(size_t)b*NP0 + q] > 0.f ? 1.f : 0.f;
                c += m;
                s += DL[(size_t)b*NP0 + q] * m;
            }
        mls = c > 0.f ? 1.f : 0.f;
        dls = c > 0.f ? s / (c + 1e-6f) : 0.f;
    }

    size_t xb = (size_t)b*6*PLANE + off;
    g_x[xb + 0*(size_t)PLANE + p] = iv0;
    g_x[xb + 1*(size_t)PLANE + p] = iv1;
    g_x[xb + 2*(size_t)PLANE + p] = iv2;
    g_x[xb + 3*(size_t)PLANE + p] = dls;
    g_x[xb + 4*(size_t)PLANE + p] = mls;
    g_x[xb + 5*(size_t)PLANE + p] = ev;
    if (FIRST) g_D[(size_t)b*NPs + p] = fminf(ev*10.f, 10.f);
}

// ---------------- init D from previous scale ----------------
__global__ void init_d_kernel(int off, int Hp, int Wp, int Hs, int Ws) {
    int NPs = Hs*Ws;
    int gid = blockIdx.x*blockDim.x + threadIdx.x;
    if (gid >= BATCH*NPs) return;
    int b = gid / NPs, p = gid % NPs;
    int y = p / Ws, x = p % Ws;

    const float* Eb = g_x + ((size_t)b*6 + 5)*PLANE + off;
    float e = Eb[p];
    float gxv = (x > 0) ? e - Eb[p-1]  : 0.f;
    float gyv = (y > 0) ? e - Eb[p-Ws] : 0.f;
    float g = fminf(0.5f*(fabsf(gxv)+fabsf(gyv)), 1.f);
    float w = 0.7f * fminf(fmaxf(1.f - g*10.f, 0.f), 1.f);

    float cy = (y + 0.5f)*0.5f - 0.5f;
    float cx = (x + 0.5f)*0.5f - 0.5f;
    int y0 = (int)floorf(cy), x0 = (int)floorf(cx);
    float fy = cy - (float)y0, fx = cx - (float)x0;
    float wyv[2] = {1.f - fy, fy};
    float wxv[2] = {1.f - fx, fx};
    const float* Dpb = g_Dp + (size_t)b*Hp*Wp;
    float wsy = 0.f, wsx = 0.f;
#pragma unroll
    for (int a = 0; a < 2; a++) if (y0+a >= 0 && y0+a < Hp) wsy += wyv[a];
#pragma unroll
    for (int a = 0; a < 2; a++) if (x0+a >= 0 && x0+a < Wp) wsx += wxv[a];
    float acc = 0.f;
#pragma unroll
    for (int a = 0; a < 2; a++) {
        int yy = y0 + a;
        if (yy < 0 || yy >= Hp) continue;
#pragma unroll
        for (int c2 = 0; c2 < 2; c2++) {
            int xx = x0 + c2;
            if (xx < 0 || xx >= Wp) continue;
            acc += wyv[a]*wxv[c2]*Dpb[(size_t)yy*Wp + xx];
        }
    }
    float up = acc / (wsy * wsx);
    float P = fminf(e*10.f, 10.f);
    g_D[(size_t)b*NPs + p] = w*up + (1.f - w)*P;
}

// ---------------- enc0 scalar conv (6->64) -> NHWC bf16 pair planes ----------------
#define CTW 32
#define CTH 8

__global__ void __launch_bounds__(256, 2) conv0_kernel(
    const float* __restrict__ in, int inPS, int inOff,
    unsigned* __restrict__ outHi, unsigned* __restrict__ outLo,
    const float* __restrict__ bias, int Hs, int Ws) {
    const int COUT = 64, NCO = 32, Cin = 6;
    __shared__ __align__(16) float s_in[Cin][CTH+2][CTW+2];
    __shared__ __align__(16) float s_w[Cin*9*COUT];

    int b  = blockIdx.z;
    int x0 = blockIdx.x*CTW, y0 = blockIdx.y*CTH;
    int tx = threadIdx.x, ty = threadIdx.y;
    int tid = ty*CTW + tx;
    int r = ty & 3, h = ty >> 2;
    int x = x0 + tx;

    unsigned long long acc[2][NCO/2];
#pragma unroll
    for (int p = 0; p < NCO/2; p++) {
        unsigned long long bv = pack2(bias[h*NCO + 2*p], bias[h*NCO + 2*p + 1]);
        acc[0][p] = bv; acc[1][p] = bv;
    }

    {
        int nW4 = Cin*9*COUT/4;
        const float4* wsrc = (const float4*)g_wT0;
        float4* wdst = (float4*)s_w;
        for (int i = tid; i < nW4; i += 256) wdst[i] = wsrc[i];
        int nI = Cin*(CTH+2)*(CTW+2);
        for (int i = tid; i < nI; i += 256) {
            int c = i / ((CTH+2)*(CTW+2));
            int rr = i % ((CTH+2)*(CTW+2));
            int iy = rr / (CTW+2), ix = rr % (CTW+2);
            int gy = y0 + iy - 1, gx = x0 + ix - 1;
            float v = 0.f;
            if (gy >= 0 && gy < Hs && gx >= 0 && gx < Ws)
                v = in[((size_t)b*6 + c)*inPS + inOff + (size_t)gy*Ws + gx];
            s_in[c][iy][ix] = v;
        }
        __syncthreads();
        for (int ci = 0; ci < Cin; ci++) {
#pragma unroll
            for (int t = 0; t < 9; t++) {
                int dy = t/3, dx = t%3;
                float a0 = s_in[ci][r     + dy][tx + dx];
                float a1 = s_in[ci][r + 4 + dy][tx + dx];
                unsigned long long v0 = pack2(a0, a0);
                unsigned long long v1 = pack2(a1, a1);
                const ulonglong2* wp = (const ulonglong2*)(s_w + (ci*9 + t)*COUT + h*NCO);
#pragma unroll
                for (int q = 0; q < NCO/4; q++) {
                    ulonglong2 wv = wp[q];
                    fma2(acc[0][2*q],   v0, wv.x);
                    fma2(acc[0][2*q+1], v0, wv.y);
                    fma2(acc[1][2*q],   v1, wv.x);
                    fma2(acc[1][2*q+1], v1, wv.y);
                }
            }
        }
    }

#pragma unroll
    for (int i = 0; i < 2; i++) {
        int y = y0 + r + 4*i;
        size_t pixBase = (((size_t)b*Hs + y)*Ws + x)*32;
#pragma unroll
        for (int p = 0; p < NCO/2; p++) {
            float lo, hi;
            unpack2(acc[i][p], lo, hi);
            lo = fmaxf(lo, 0.f); hi = fmaxf(hi, 0.f);
            unsigned short h0, l0, h1, l1;
            bfsplit(lo, h0, l0);
            bfsplit(hi, h1, l1);
            outHi[pixBase + h*16 + p] = (unsigned)h0 | ((unsigned)h1 << 16);
            outLo[pixBase + h*16 + p] = (unsigned)l0 | ((unsigned)l1 << 16);
        }
    }
}

// ---------------- mma conv: 16x16 px tile, 8 warps, 3-tap weight groups (sync staging) ----------------
// smem: s_w [3*NT*8 rows][72 u16], s_h [324 px (18x18)][72 u16].
__device__ __forceinline__ void load_halo(unsigned short* s_h, const unsigned* __restrict__ src,
                                          int b, int x0, int y0, int Hs, int Ws, int tid) {
    // vectorized: 4 channel-pair words per iteration (16B)
    for (int i = tid; i < 324*8; i += 256) {
        int px = i >> 3, j4 = i & 7;
        int hy = px / 18, hx = px % 18;
        int gy = y0 + hy - 1, gx = x0 + hx - 1;
        uint4 v = make_uint4(0u, 0u, 0u, 0u);
        if (gy >= 0 && gy < Hs && gx >= 0 && gx < Ws) {
            size_t base = (((size_t)b*Hs + gy)*Ws + gx)*32;
            v = ((const uint4*)(src + base))[j4];
        }
        *(uint4*)(s_h + px*72 + 8*j4) = v;
    }
}

// mma over one 3-tap group (dy = grp, dx = 0..2)
template<int NT>
__device__ __forceinline__ void mma_group(unsigned sw_addr, unsigned sh_addr, int grp,
                                          float (&acc)[2][NT][4], int w, int lane) {
    int m  = lane & 15, kh = lane >> 4;
    int br = lane & 7, bkh = (lane >> 3) & 1, bt = lane >> 4;
    int dy = grp;
#pragma unroll
    for (int dx = 0; dx < 3; dx++) {
#pragma unroll
        for (int kc = 0; kc < 4; kc++) {
            unsigned a[2][4];
#pragma unroll
            for (int r = 0; r < 2; r++) {
                unsigned addr = sh_addr +
                    ((unsigned)(((2*w + r + dy)*18 + m + dx)*72 + kc*16 + kh*8))*2u;
                ldsm_x4(a[r][0], a[r][1], a[r][2], a[r][3], addr);
            }
#pragma unroll
            for (int np = 0; np < NT/2; np++) {
                unsigned b0, b1, b2, b3;
                unsigned baddr = sw_addr +
                    ((unsigned)(((dx*NT + np*2 + bt)*8 + br)*72 + kc*16 + bkh*8))*2u;
                ldsm_x4(b0, b1, b2, b3, baddr);
#pragma unroll
                for (int r = 0; r < 2; r++) {
                    mma16816(acc[r][2*np][0],   acc[r][2*np][1],   acc[r][2*np][2],   acc[r][2*np][3],
                             a[r][0], a[r][1], a[r][2], a[r][3], b0, b1);
                    mma16816(acc[r][2*np+1][0], acc[r][2*np+1][1], acc[r][2*np+1][2], acc[r][2*np+1][3],
                             a[r][0], a[r][1], a[r][2], a[r][3], b2, b3);
                }
            }
        }
    }
}

// MODE 0: relu + NHWC pair-plane out. MODE 1: fused head epilogue (NT=4).
template<int NT, int MODE>
__global__ void __launch_bounds__(256) tconv_mma(
    const unsigned* __restrict__ inHi, const unsigned* __restrict__ inLo,
    const unsigned* __restrict__ wHi, const unsigned* __restrict__ wLo,
    const float* __restrict__ bias,
    unsigned* __restrict__ outHi, unsigned* __restrict__ outLo,
    int outOff, int Hs, int Ws) {
    extern __shared__ __align__(16) unsigned short sm[];
    unsigned short* s_w = sm;                    // 3*NT*8*72 u16
    unsigned short* s_h = sm + 3*NT*8*72;        // 324*72 u16
    const int GCNT4 = 3*NT*8*9;                  // uint4 per weight group

    int tid = threadIdx.x;
    int w = tid >> 5, lane = tid & 31, g = lane >> 2, t4 = lane & 3;
    int b = blockIdx.z;
    int x0 = blockIdx.x*16, y0 = blockIdx.y*16;
    unsigned sw_addr = smem_u32(s_w);
    unsigned sh_addr = smem_u32(s_h);

    float acc[2][NT][4];
#pragma unroll
    for (int r = 0; r < 2; r++)
#pragma unroll
        for (int nt = 0; nt < NT; nt++)
#pragma unroll
            for (int q = 0; q < 4; q++) acc[r][nt][q] = 0.f;

    // phases: (halo=Hi,w=Hi), (halo=Hi,w=Lo), (halo=Lo,w=Hi)
#pragma unroll
    for (int ph = 0; ph < 3; ph++) {
        const unsigned* wsrc = (ph == 1) ? wLo : wHi;
        if (ph == 0 || ph == 2) {
            if (ph == 2) __syncthreads();   // prior mma done before halo overwrite
            load_halo(s_h, (ph == 0) ? inHi : inLo, b, x0, y0, Hs, Ws, tid);
        }
        for (int grp = 0; grp < 3; grp++) {
            __syncthreads();                // prev group mma (and halo load) complete
            const uint4* src4 = (const uint4*)(wsrc) + grp*GCNT4;
            uint4* dst4 = (uint4*)s_w;
            for (int i = tid; i < GCNT4; i += 256) dst4[i] = src4[i];
            __syncthreads();
            mma_group<NT>(sw_addr, sh_addr, grp, acc, w, lane);
        }
    }

    if (MODE == 0) {
#pragma unroll
        for (int r = 0; r < 2; r++) {
            int y = y0 + 2*w + r;
            if (y >= Hs) continue;
            size_t rowBase = ((size_t)b*Hs + y)*Ws;
            size_t p0 = (rowBase + x0 + g)*32;
            size_t p1 = (rowBase + x0 + g + 8)*32;
#pragma unroll
            for (int nt = 0; nt < NT; nt++) {
                int c = nt*8 + t4*2;
                float b0v = bias[c], b1v = bias[c+1];
                float v0 = fmaxf(acc[r][nt][0] + b0v, 0.f);
                float v1 = fmaxf(acc[r][nt][1] + b1v, 0.f);
                float v2 = fmaxf(acc[r][nt][2] + b0v, 0.f);
                float v3 = fmaxf(acc[r][nt][3] + b1v, 0.f);
                unsigned short h0,l0,h1,l1,h2,l2,h3,l3;
                bfsplit(v0,h0,l0); bfsplit(v1,h1,l1);
                bfsplit(v2,h2,l2); bfsplit(v3,h3,l3);
                outHi[p0 + nt*4 + t4] = (unsigned)h0 | ((unsigned)h1 << 16);
                outLo[p0 + nt*4 + t4] = (unsigned)l0 | ((unsigned)l1 << 16);
                outHi[p1 + nt*4 + t4] = (unsigned)h2 | ((unsigned)h3 << 16);
                outLo[p1 + nt*4 + t4] = (unsigned)l2 | ((unsigned)l3 << 16);
            }
        }
    } else {
        __syncthreads();
        float* s_d = (float*)s_h;   // 256 px * 33 f32 = 33.8KB <= halo area (46.6KB)
#pragma unroll
        for (int r = 0; r < 2; r++) {
            int pl0 = (2*w + r)*16 + g;
#pragma unroll
            for (int nt = 0; nt < NT; nt++) {
                int c = nt*8 + t4*2;
                s_d[pl0*33 + c]       = acc[r][nt][0];
                s_d[pl0*33 + c + 1]   = acc[r][nt][1];
                s_d[(pl0+8)*33 + c]   = acc[r][nt][2];
                s_d[(pl0+8)*33 + c+1] = acc[r][nt][3];
            }
        }
        __syncthreads();
        int yl = tid / 16, xl = tid % 16;
        int y = y0 + yl;
        if (y >= Hs) return;
        float a[30];
#pragma unroll
        for (int c = 0; c < 30; c++) a[c] = s_d[tid*33 + c] + g_bagc[c];
        size_t pp = (size_t)y*Ws + (x0 + xl);
        size_t Ab = (size_t)b*24*PLANE + outOff + pp;
        size_t Cb = (size_t)b*9*PLANE  + outOff + pp;
#pragma unroll
        for (int k = 0; k < 3; k++) {
            float sab = 1e-6f;
#pragma unroll
            for (int j = 0; j < 8; j++) sab += fabsf(a[k*8+j]);
            float inv = 1.f / sab, sms = 0.f;
#pragma unroll
            for (int j = 0; j < 8; j++) {
                float an = a[k*8+j]*inv;
                g_A[Ab + (size_t)(k*8+j)*PLANE] = an;
                sms += an;
            }
            g_csk[Cb + (size_t)k*PLANE] = 1.f - sms;
        }
        float g0 = a[24], g1 = a[25], g2 = a[26];
        float m = fmaxf(g0, fmaxf(g1, g2));
        float e0 = expf(g0 - m), e1 = expf(g1 - m), e2 = expf(g2 - m);
        float inv = 1.f / (e0 + e1 + e2);
        g_csk[Cb + 3*(size_t)PLANE] = e0*inv;
        g_csk[Cb + 4*(size_t)PLANE] = e1*inv;
        g_csk[Cb + 5*(size_t)PLANE] = e2*inv;
        size_t Vb = (size_t)b*3*PLANE + outOff + pp;
#pragma unroll
        for (int k = 0; k < 3; k++)
            g_curv[Vb + (size_t)k*PLANE] = a[27+k];
    }
}

// ---------------- curv D-part ----------------
__global__ void curvd_kernel(const float* __restrict__ wc, int off, int Hs, int Ws) {
    int NPs = Hs*Ws;
    int gid = blockIdx.x*blockDim.x + threadIdx.x;
    if (gid >= BATCH*NPs) return;
    int b = gid / NPs, p = gid % NPs;
    int y = p / Ws, x = p % Ws;
    const float* Db = g_D + (size_t)b*NPs;
    float dnb[9];
#pragma unroll
    for (int t = 0; t < 9; t++) {
        int dy = t/3 - 1, dx = t%3 - 1;
        int ny = y + dy, nx = x + dx;
        dnb[t] = (ny >= 0 && ny < Hs && nx >= 0 && nx < Ws) ? Db[(size_t)ny*Ws + nx]*0.1f : 0.f;
    }
    size_t Vb = (size_t)b*3*PLANE + off + p;
    size_t Cb = (size_t)b*9*PLANE + off + p;
#pragma unroll
    for (int co = 0; co < 3; co++) {
        float v = g_curv[Vb + (size_t)co*PLANE];
#pragma unroll
        for (int t = 0; t < 9; t++)
            v += wc[((size_t)co*65 + 64)*9 + t] * dnb[t];
        g_csk[Cb + (size_t)(6+co)*PLANE] = 0.1f + 0.9f/(1.f + expf(-v));
    }
}

// ---------------- propagation step ----------------
__global__ void prop_kernel(const float* __restrict__ Din, float* __restrict__ Dout,
                            int off, int Hs, int Ws) {
    int NPs = Hs*Ws;
    int gid = blockIdx.x*blockDim.x + threadIdx.x;
    if (gid >= BATCH*NPs) return;
    int b = gid / NPs, p = gid % NPs;
    int y = p / Ws, x = p % Ws;
    const float* Db = Din + (size_t)b*NPs;
    float d = Db[p];
    size_t Ab = (size_t)b*24*PLANE + off + p;
    size_t Cb = (size_t)b*9*PLANE + off + p;
    const int offy[8] = {-1,-1,-1, 0, 0, 1, 1, 1};
    const int offx[8] = {-1, 0, 1,-1, 1,-1, 0, 1};
    const int dil[3]  = {1, 2, 4};
    float mix = 0.f;
#pragma unroll
    for (int k = 0; k < 3; k++) {
        float agg = g_csk[Cb + (size_t)k*PLANE] * d;
        int dd = dil[k];
#pragma unroll
        for (int j = 0; j < 8; j++) {
            int ny = y + offy[j]*dd, nx = x + offx[j]*dd;
            float nb = (ny >= 0 && ny < Hs && nx >= 0 && nx < Ws) ? Db[(size_t)ny*Ws + nx] : 0.f;
            agg += g_A[Ab + (size_t)(k*8+j)*PLANE] * nb;
        }
        float sig = g_csk[Cb + (size_t)(3+k)*PLANE];
        float kap = g_csk[Cb + (size_t)(6+k)*PLANE];
        mix += sig * (d + kap*(agg - d));
    }
    size_t xb = (size_t)b*6*PLANE + off + p;
    float dls = g_x[xb + 3*(size_t)PLANE];
    float mls = g_x[xb + 4*(size_t)PLANE];
    Dout[(size_t)b*NPs + p] = mls*(0.9f*dls + 0.1f*mix) + (1.f - mls)*mix;
}

// ---------------- host orchestration ----------------
extern "C" void kernel_launch(void* const* d_in, const int* in_sizes, int n_in,
                              void* d_out, int out_size) {
    (void)in_sizes; (void)n_in; (void)out_size;
    const float* I  = (const float*)d_in[0];
    const float* DL = (const float*)d_in[1];
    const float* ML = (const float*)d_in[2];
    const float* E  = (const float*)d_in[3];
    const float* w0 = (const float*)d_in[4];
    const float* b0 = (const float*)d_in[5];
    const float* w1 = (const float*)d_in[6];
    const float* b1 = (const float*)d_in[7];
    const float* w2 = (const float*)d_in[8];
    const float* b2 = (const float*)d_in[9];
    const float* wa = (const float*)d_in[10];
    const float* ba = (const float*)d_in[11];
    const float* wg = (const float*)d_in[12];
    const float* bg = (const float*)d_in[13];
    const float* wc = (const float*)d_in[14];
    const float* bc = (const float*)d_in[15];
    float* out = (float*)d_out;

    float *px, *pD, *pD2, *pDp, *pbagc;
    unsigned *pfh0, *pfl0, *pfh1, *pfl1;
    unsigned *pWh1, *pWl1, *pWh2, *pWl2, *pWha, *pWla;
    cudaGetSymbolAddress((void**)&px,   g_x);
    cudaGetSymbolAddress((void**)&pD,   g_D);
    cudaGetSymbolAddress((void**)&pD2,  g_D2);
    cudaGetSymbolAddress((void**)&pDp,  g_Dp);
    cudaGetSymbolAddress((void**)&pbagc, g_bagc);
    cudaGetSymbolAddress((void**)&pfh0, g_fh0);
    cudaGetSymbolAddress((void**)&pfl0, g_fl0);
    cudaGetSymbolAddress((void**)&pfh1, g_fh1);
    cudaGetSymbolAddress((void**)&pfl1, g_fl1);
    cudaGetSymbolAddress((void**)&pWh1, g_WH1);
    cudaGetSymbolAddress((void**)&pWl1, g_WL1);
    cudaGetSymbolAddress((void**)&pWh2, g_WH2);
    cudaGetSymbolAddress((void**)&pWl2, g_WL2);
    cudaGetSymbolAddress((void**)&pWha, g_WHa);
    cudaGetSymbolAddress((void**)&pWla, g_WLa);

    const int SM_ENC = (3*8*8*72 + 324*72)*2;   // 74,304 B
    const int SM_AGC = (3*4*8*72 + 324*72)*2;   // 60,480 B
    cudaFuncSetAttribute(tconv_mma<8,0>, cudaFuncAttributeMaxDynamicSharedMemorySize, SM_ENC);
    cudaFuncSetAttribute(tconv_mma<4,1>, cudaFuncAttributeMaxDynamicSharedMemorySize, SM_AGC);

    const int SC[3]   = {4, 2, 1};
    const int OFFS[3] = {OFF_S4, OFF_S2, OFF_S1};

    // launch 0: weight prep ; launch 1: s=1 input prep
    prep_weights<<<(95616 + 255)/256, 256>>>(w0, w1, w2, wa, ba, wg, bg, wc, bc);
    {
        int tot = BATCH*H0*W0;
        prep_kernel<1, false><<<(tot+255)/256, 256>>>(I, DL, ML, E, OFF_S1, H0, W0);
    }

    // convs: s=1 first (launch 2 = conv0 scalar, launch 3 = enc1 mma for ncu)
    for (int si = 2; si >= 0; si--) {
        int S = SC[si];
        int off = OFFS[si];
        int Hs = H0/S, Ws = W0/S;
        if (si == 1) {
            int tot = BATCH*Hs*Ws;
            prep_kernel<2, false><<<(tot+255)/256, 256>>>(I, DL, ML, E, OFF_S2, Hs, Ws);
        } else if (si == 0) {
            int tot = BATCH*Hs*Ws;
            prep_kernel<4, true><<<(tot+255)/256, 256>>>(I, DL, ML, E, OFF_S4, Hs, Ws);
        }
        dim3 cb0(CTW, 8);
        dim3 cg0(Ws/CTW, Hs/CTH, BATCH);
        conv0_kernel<<<cg0, cb0>>>(px, PLANE, off, pfh0, pfl0, b0, Hs, Ws);
        dim3 tg(Ws/16, (Hs + 15)/16, BATCH);
        tconv_mma<8,0><<<tg, 256, SM_ENC>>>(pfh0, pfl0, pWh1, pWl1, b1, pfh1, pfl1, 0, Hs, Ws);
        tconv_mma<8,0><<<tg, 256, SM_ENC>>>(pfh1, pfl1, pWh2, pWl2, b2, pfh0, pfl0, 0, Hs, Ws);
        tconv_mma<4,1><<<tg, 256, SM_AGC>>>(pfh0, pfl0, pWha, pWla, pbagc, nullptr, nullptr, off, Hs, Ws);
    }

    // propagation chain: coarse-to-fine
    int Hp = 0, Wp = 0;
    for (int si = 0; si < 3; si++) {
        int S = SC[si];
        int off = OFFS[si];
        int Hs = H0/S, Ws = W0/S, NPs = Hs*Ws;
        int tot = BATCH*NPs, blk = (tot + 255)/256;

        if (si > 0) init_d_kernel<<<blk, 256>>>(off, Hp, Wp, Hs, Ws);
        curvd_kernel<<<blk, 256>>>(wc, off, Hs, Ws);

        float* Dc = pD;
        float* Dn = pD2;
        for (int st = 0; st < 6; st++) {
            prop_kernel<<<blk, 256>>>(Dc, Dn, off, Hs, Ws);
            float* t = Dc; Dc = Dn; Dn = t;
        }
        if (si < 2) {
            cudaMemcpyAsync(pDp, Dc, sizeof(float)*(size_t)BATCH*NPs, cudaMemcpyDeviceToDevice);
        } else {
            cudaMemcpyAsync(out, Dc, sizeof(float)*(size_t)BATCH*NPs, cudaMemcpyDeviceToDevice);
        }
        Hp = Hs; Wp = Ws;
    }
}

// round 16
// speedup vs baseline: 1.2255x; 1.2255x over previous
#include <cuda_runtime.h>
#include <cuda_bf16.h>
#include <math.h>
#include <stdint.h>

#define BATCH 2
#define H0 480
#define W0 640
#define NP0 (H0*W0)

#define PLANE 403200
#define OFF_S4 0
#define OFF_S2 19200
#define OFF_S1 96000

// ---------------- scratch (device globals) ----------------
__device__ float g_x   [BATCH*6 *PLANE];
__device__ float g_A   [BATCH*24*PLANE];
__device__ float g_csk [BATCH*9 *PLANE];
__device__ float g_curv[BATCH*3 *PLANE];
__device__ float g_D   [BATCH*NP0];
__device__ float g_D2  [BATCH*NP0];
__device__ float g_Dp  [BATCH*NP0];

// activations NHWC bf16 pair-planes: u32 = (bf16 ch c | bf16 ch c+1 << 16), 32 pairs
__device__ __align__(16) unsigned g_fh0[BATCH*NP0*32];
__device__ __align__(16) unsigned g_fl0[BATCH*NP0*32];
__device__ __align__(16) unsigned g_fh1[BATCH*NP0*32];
__device__ __align__(16) unsigned g_fl1[BATCH*NP0*32];

// enc0 scalar weights [ci][tap][co]
__device__ float g_wT0[6*9*64];
// mma weights prepacked [tap][co][ci pad 72] bf16 (hi / lo), 36 u32 per row
__device__ __align__(16) unsigned g_WH1[9*64*36];
__device__ __align__(16) unsigned g_WL1[9*64*36];
__device__ __align__(16) unsigned g_WH2[9*64*36];
__device__ __align__(16) unsigned g_WL2[9*64*36];
__device__ __align__(16) unsigned g_WHa[9*32*36];
__device__ __align__(16) unsigned g_WLa[9*32*36];
__device__ float g_bagc[32];

// ---------------- helpers ----------------
__device__ __forceinline__ uint32_t smem_u32(const void* p) {
    uint32_t a;
    asm("{ .reg .u64 t; cvta.to.shared.u64 t, %1; cvt.u32.u64 %0, t; }" : "=r"(a) : "l"(p));
    return a;
}
__device__ __forceinline__ void fma2(unsigned long long& d, unsigned long long a, unsigned long long b) {
    asm("fma.rn.f32x2 %0, %1, %2, %0;" : "+l"(d) : "l"(a), "l"(b));
}
__device__ __forceinline__ unsigned long long pack2(float lo, float hi) {
    unsigned long long r;
    asm("mov.b64 %0, {%1, %2};" : "=l"(r) : "f"(lo), "f"(hi));
    return r;
}
__device__ __forceinline__ void unpack2(unsigned long long v, float& lo, float& hi) {
    asm("mov.b64 {%0, %1}, %2;" : "=f"(lo), "=f"(hi) : "l"(v));
}
__device__ __forceinline__ void bfsplit(float v, unsigned short& h, unsigned short& l) {
    __nv_bfloat16 bh = __float2bfloat16_rn(v);
    float r = v - __bfloat162float(bh);
    __nv_bfloat16 bl = __float2bfloat16_rn(r);
    h = __bfloat16_as_ushort(bh);
    l = __bfloat16_as_ushort(bl);
}
__device__ __forceinline__ void mma16816(float& c0, float& c1, float& c2, float& c3,
                                         unsigned a0, unsigned a1, unsigned a2, unsigned a3,
                                         unsigned b0, unsigned b1) {
    asm volatile("mma.sync.aligned.m16n8k16.row.col.f32.bf16.bf16.f32 "
        "{%0,%1,%2,%3}, {%4,%5,%6,%7}, {%8,%9}, {%0,%1,%2,%3};"
        : "+f"(c0), "+f"(c1), "+f"(c2), "+f"(c3)
        : "r"(a0), "r"(a1), "r"(a2), "r"(a3), "r"(b0), "r"(b1));
}
__device__ __forceinline__ void ldsm_x4(unsigned& r0, unsigned& r1, unsigned& r2, unsigned& r3,
                                        unsigned addr) {
    asm volatile("ldmatrix.sync.aligned.m8n8.x4.shared.b16 {%0,%1,%2,%3}, [%4];"
        : "=r"(r0), "=r"(r1), "=r"(r2), "=r"(r3) : "r"(addr));
}

// ---------------- weight prep ----------------
__global__ void prep_weights(const float* __restrict__ w0,
                             const float* __restrict__ w1, const float* __restrict__ w2,
                             const float* __restrict__ wa, const float* __restrict__ ba,
                             const float* __restrict__ wg, const float* __restrict__ bg,
                             const float* __restrict__ wc, const float* __restrict__ bc) {
    int i = blockIdx.x*blockDim.x + threadIdx.x;
    if (i < 32) {
        float bv = 0.f;
        if (i < 24) bv = ba[i];
        else if (i < 27) bv = bg[i-24];
        else if (i < 30) bv = bc[i-27];
        g_bagc[i] = bv;
    }
    if (i < 3456) {                                  // enc0 OIHW -> [ci][t][co]
        int co = i / 54, r = i % 54, ci = r / 9, t = r % 9;
        g_wT0[(ci*9 + t)*64 + co] = w0[i];
    } else if (i < 40320) {                          // enc1: [tap][co][ci72]
        int j = i - 3456;
        int t = j / 4096, rem = j % 4096, co = rem / 64, ci = rem % 64;
        float v = w1[((size_t)co*64 + ci)*9 + t];
        unsigned short h, l; bfsplit(v, h, l);
        int idx = (t*64 + co)*72 + ci;
        ((unsigned short*)g_WH1)[idx] = h;
        ((unsigned short*)g_WL1)[idx] = l;
    } else if (i < 77184) {                          // enc2
        int j = i - 40320;
        int t = j / 4096, rem = j % 4096, co = rem / 64, ci = rem % 64;
        float v = w2[((size_t)co*64 + ci)*9 + t];
        unsigned short h, l; bfsplit(v, h, l);
        int idx = (t*64 + co)*72 + ci;
        ((unsigned short*)g_WH2)[idx] = h;
        ((unsigned short*)g_WL2)[idx] = l;
    } else if (i < 77184 + 18432) {                  // agc: 32 co
        int j = i - 77184;
        int t = j / 2048, rem = j % 2048, co = rem / 64, ci = rem % 64;
        float v = 0.f;
        if (co < 24)      v = wa[((size_t)co*64 + ci)*9 + t];
        else if (co < 27) v = wg[((size_t)(co-24)*64 + ci)*9 + t];
        else if (co < 30) v = wc[((size_t)(co-27)*65 + ci)*9 + t];
        unsigned short h, l; bfsplit(v, h, l);
        int idx = (t*32 + co)*72 + ci;
        ((unsigned short*)g_WHa)[idx] = h;
        ((unsigned short*)g_WLa)[idx] = l;
    }
}

// ---------------- antialiased downsample weights ----------------
template<int F>
__device__ __forceinline__ void down_weights(int i, int n, int& j0, float* w, float& ws) {
    float c = (float)(F*i) + 0.5f*(float)F - 0.5f;
    j0 = (int)ceilf(c - (float)F);
    ws = 0.f;
#pragma unroll
    for (int t = 0; t < 2*F; t++) {
        int j = j0 + t;
        float wv = (j >= 0 && j < n) ? (1.f - fabsf((float)j - c) * (1.f/(float)F)) : 0.f;
        w[t] = wv; ws += wv;
    }
}

// ---------------- per-scale input prep ----------------
template<int S, bool FIRST>
__global__ void prep_kernel(const float* __restrict__ I, const float* __restrict__ DL,
                            const float* __restrict__ ML, const float* __restrict__ E,
                            int off, int Hs, int Ws) {
    int NPs = Hs*Ws;
    int gid = blockIdx.x*blockDim.x + threadIdx.x;
    if (gid >= BATCH*NPs) return;
    int b = gid / NPs, p = gid % NPs;
    int y = p / Ws, x = p % Ws;

    float iv0, iv1, iv2, ev;
    if (S == 1) {
        const float* Ib = I + (size_t)b*3*NP0;
        iv0 = Ib[p]; iv1 = Ib[NP0 + p]; iv2 = Ib[2*NP0 + p];
        ev  = E[(size_t)b*NP0 + p];
    } else {
        float wy[2*S], wx[2*S], wys, wxs;
        int jy0, jx0;
        down_weights<S>(y, H0, jy0, wy, wys);
        down_weights<S>(x, W0, jx0, wx, wxs);
        float a0=0.f, a1=0.f, a2=0.f, ae=0.f;
        const float* Ib = I + (size_t)b*3*NP0;
        const float* Eb = E + (size_t)b*NP0;
#pragma unroll
        for (int ty = 0; ty < 2*S; ty++) {
            int yy = jy0 + ty;
            if (yy < 0 || yy >= H0) continue;
            float wyv = wy[ty];
#pragma unroll
            for (int tx = 0; tx < 2*S; tx++) {
                int xx = jx0 + tx;
                if (xx < 0 || xx >= W0) continue;
                float wv = wyv * wx[tx];
                int q = yy*W0 + xx;
                a0 += wv*Ib[q]; a1 += wv*Ib[NP0 + q]; a2 += wv*Ib[2*NP0 + q]; ae += wv*Eb[q];
            }
        }
        float inv = 1.f / (wys * wxs);
        iv0 = a0*inv; iv1 = a1*inv; iv2 = a2*inv; ev = ae*inv;
    }
    ev = fminf(fmaxf(ev, 0.f), 1.f);

    float dls, mls;
    if (S == 1) {
        mls = ML[(size_t)b*NP0 + p] > 0.f ? 1.f : 0.f;
        dls = DL[(size_t)b*NP0 + p];
    } else {
        float s = 0.f, c = 0.f;
        for (int dy = 0; dy < S; dy++)
            for (int dx = 0; dx < S; dx++) {
                int q = (y*S + dy)*W0 + (x*S + dx);
                float m = ML[(size_t)b*NP0 + q] > 0.f ? 1.f : 0.f;
                c += m;
                s += DL[(size_t)b*NP0 + q] * m;
            }
        mls = c > 0.f ? 1.f : 0.f;
        dls = c > 0.f ? s / (c + 1e-6f) : 0.f;
    }

    size_t xb = (size_t)b*6*PLANE + off;
    g_x[xb + 0*(size_t)PLANE + p] = iv0;
    g_x[xb + 1*(size_t)PLANE + p] = iv1;
    g_x[xb + 2*(size_t)PLANE + p] = iv2;
    g_x[xb + 3*(size_t)PLANE + p] = dls;
    g_x[xb + 4*(size_t)PLANE + p] = mls;
    g_x[xb + 5*(size_t)PLANE + p] = ev;
    if (FIRST) g_D[(size_t)b*NPs + p] = fminf(ev*10.f, 10.f);
}

// ---------------- init D from previous scale ----------------
__global__ void init_d_kernel(int off, int Hp, int Wp, int Hs, int Ws) {
    int NPs = Hs*Ws;
    int gid = blockIdx.x*blockDim.x + threadIdx.x;
    if (gid >= BATCH*NPs) return;
    int b = gid / NPs, p = gid % NPs;
    int y = p / Ws, x = p % Ws;

    const float* Eb = g_x + ((size_t)b*6 + 5)*PLANE + off;
    float e = Eb[p];
    float gxv = (x > 0) ? e - Eb[p-1]  : 0.f;
    float gyv = (y > 0) ? e - Eb[p-Ws] : 0.f;
    float g = fminf(0.5f*(fabsf(gxv)+fabsf(gyv)), 1.f);
    float w = 0.7f * fminf(fmaxf(1.f - g*10.f, 0.f), 1.f);

    float cy = (y + 0.5f)*0.5f - 0.5f;
    float cx = (x + 0.5f)*0.5f - 0.5f;
    int y0 = (int)floorf(cy), x0 = (int)floorf(cx);
    float fy = cy - (float)y0, fx = cx - (float)x0;
    float wyv[2] = {1.f - fy, fy};
    float wxv[2] = {1.f - fx, fx};
    const float* Dpb = g_Dp + (size_t)b*Hp*Wp;
    float wsy = 0.f, wsx = 0.f;
#pragma unroll
    for (int a = 0; a < 2; a++) if (y0+a >= 0 && y0+a < Hp) wsy += wyv[a];
#pragma unroll
    for (int a = 0; a < 2; a++) if (x0+a >= 0 && x0+a < Wp) wsx += wxv[a];
    float acc = 0.f;
#pragma unroll
    for (int a = 0; a < 2; a++) {
        int yy = y0 + a;
        if (yy < 0 || yy >= Hp) continue;
#pragma unroll
        for (int c2 = 0; c2 < 2; c2++) {
            int xx = x0 + c2;
            if (xx < 0 || xx >= Wp) continue;
            acc += wyv[a]*wxv[c2]*Dpb[(size_t)yy*Wp + xx];
        }
    }
    float up = acc / (wsy * wsx);
    float P = fminf(e*10.f, 10.f);
    g_D[(size_t)b*NPs + p] = w*up + (1.f - w)*P;
}

// ---------------- enc0 scalar conv (6->64) -> NHWC bf16 pair planes ----------------
#define CTW 32
#define CTH 8

__global__ void __launch_bounds__(256, 2) conv0_kernel(
    const float* __restrict__ in, int inPS, int inOff,
    unsigned* __restrict__ outHi, unsigned* __restrict__ outLo,
    const float* __restrict__ bias, int Hs, int Ws) {
    const int COUT = 64, NCO = 32, Cin = 6;
    __shared__ __align__(16) float s_in[Cin][CTH+2][CTW+2];
    __shared__ __align__(16) float s_w[Cin*9*COUT];

    int b  = blockIdx.z;
    int x0 = blockIdx.x*CTW, y0 = blockIdx.y*CTH;
    int tx = threadIdx.x, ty = threadIdx.y;
    int tid = ty*CTW + tx;
    int r = ty & 3, h = ty >> 2;
    int x = x0 + tx;

    unsigned long long acc[2][NCO/2];
#pragma unroll
    for (int p = 0; p < NCO/2; p++) {
        unsigned long long bv = pack2(bias[h*NCO + 2*p], bias[h*NCO + 2*p + 1]);
        acc[0][p] = bv; acc[1][p] = bv;
    }

    {
        int nW4 = Cin*9*COUT/4;
        const float4* wsrc = (const float4*)g_wT0;
        float4* wdst = (float4*)s_w;
        for (int i = tid; i < nW4; i += 256) wdst[i] = wsrc[i];
        int nI = Cin*(CTH+2)*(CTW+2);
        for (int i = tid; i < nI; i += 256) {
            int c = i / ((CTH+2)*(CTW+2));
            int rr = i % ((CTH+2)*(CTW+2));
            int iy = rr / (CTW+2), ix = rr % (CTW+2);
            int gy = y0 + iy - 1, gx = x0 + ix - 1;
            float v = 0.f;
            if (gy >= 0 && gy < Hs && gx >= 0 && gx < Ws)
                v = in[((size_t)b*6 + c)*inPS + inOff + (size_t)gy*Ws + gx];
            s_in[c][iy][ix] = v;
        }
        __syncthreads();
        for (int ci = 0; ci < Cin; ci++) {
#pragma unroll
            for (int t = 0; t < 9; t++) {
                int dy = t/3, dx = t%3;
                float a0 = s_in[ci][r     + dy][tx + dx];
                float a1 = s_in[ci][r + 4 + dy][tx + dx];
                unsigned long long v0 = pack2(a0, a0);
                unsigned long long v1 = pack2(a1, a1);
                const ulonglong2* wp = (const ulonglong2*)(s_w + (ci*9 + t)*COUT + h*NCO);
#pragma unroll
                for (int q = 0; q < NCO/4; q++) {
                    ulonglong2 wv = wp[q];
                    fma2(acc[0][2*q],   v0, wv.x);
                    fma2(acc[0][2*q+1], v0, wv.y);
                    fma2(acc[1][2*q],   v1, wv.x);
                    fma2(acc[1][2*q+1], v1, wv.y);
                }
            }
        }
    }

#pragma unroll
    for (int i = 0; i < 2; i++) {
        int y = y0 + r + 4*i;
        size_t pixBase = (((size_t)b*Hs + y)*Ws + x)*32;
#pragma unroll
        for (int p = 0; p < NCO/2; p++) {
            float lo, hi;
            unpack2(acc[i][p], lo, hi);
            lo = fmaxf(lo, 0.f); hi = fmaxf(hi, 0.f);
            unsigned short h0, l0, h1, l1;
            bfsplit(lo, h0, l0);
            bfsplit(hi, h1, l1);
            outHi[pixBase + h*16 + p] = (unsigned)h0 | ((unsigned)h1 << 16);
            outLo[pixBase + h*16 + p] = (unsigned)l0 | ((unsigned)l1 << 16);
        }
    }
}

// ---------------- mma conv: 16x16 px tile, 8 warps, 3-tap weight groups (sync staging) ----------------
// smem: s_w [3*NT*8 rows][72 u16], s_h [324 px (18x18)][72 u16].
__device__ __forceinline__ void load_halo(unsigned short* s_h, const unsigned* __restrict__ src,
                                          int b, int x0, int y0, int Hs, int Ws, int tid) {
    // vectorized: 4 channel-pair words per iteration (16B)
    for (int i = tid; i < 324*8; i += 256) {
        int px = i >> 3, j4 = i & 7;
        int hy = px / 18, hx = px % 18;
        int gy = y0 + hy - 1, gx = x0 + hx - 1;
        uint4 v = make_uint4(0u, 0u, 0u, 0u);
        if (gy >= 0 && gy < Hs && gx >= 0 && gx < Ws) {
            size_t base = (((size_t)b*Hs + gy)*Ws + gx)*32;
            v = ((const uint4*)(src + base))[j4];
        }
        *(uint4*)(s_h + px*72 + 8*j4) = v;
    }
}

// mma over one 3-tap group (dy = grp, dx = 0..2)
template<int NT>
__device__ __forceinline__ void mma_group(unsigned sw_addr, unsigned sh_addr, int grp,
                                          float (&acc)[2][NT][4], int w, int lane) {
    int m  = lane & 15, kh = lane >> 4;
    int br = lane & 7, bkh = (lane >> 3) & 1, bt = lane >> 4;
    int dy = grp;
#pragma unroll
    for (int dx = 0; dx < 3; dx++) {
#pragma unroll
        for (int kc = 0; kc < 4; kc++) {
            unsigned a[2][4];
#pragma unroll
            for (int r = 0; r < 2; r++) {
                unsigned addr = sh_addr +
                    ((unsigned)(((2*w + r + dy)*18 + m + dx)*72 + kc*16 + kh*8))*2u;
                ldsm_x4(a[r][0], a[r][1], a[r][2], a[r][3], addr);
            }
#pragma unroll
            for (int np = 0; np < NT/2; np++) {
                unsigned b0, b1, b2, b3;
                unsigned baddr = sw_addr +
                    ((unsigned)(((dx*NT + np*2 + bt)*8 + br)*72 + kc*16 + bkh*8))*2u;
                ldsm_x4(b0, b1, b2, b3, baddr);
#pragma unroll
                for (int r = 0; r < 2; r++) {
                    mma16816(acc[r][2*np][0],   acc[r][2*np][1],   acc[r][2*np][2],   acc[r][2*np][3],
                             a[r][0], a[r][1], a[r][2], a[r][3], b0, b1);
                    mma16816(acc[r][2*np+1][0], acc[r][2*np+1][1], acc[r][2*np+1][2], acc[r][2*np+1][3],
                             a[r][0], a[r][1], a[r][2], a[r][3], b2, b3);
                }
            }
        }
    }
}

// MODE 0: relu + NHWC pair-plane out. MODE 1: fused head epilogue (NT=4).
template<int NT, int MODE>
__global__ void __launch_bounds__(256, 2) tconv_mma(
    const unsigned* __restrict__ inHi, const unsigned* __restrict__ inLo,
    const unsigned* __restrict__ wHi, const unsigned* __restrict__ wLo,
    const float* __restrict__ bias,
    unsigned* __restrict__ outHi, unsigned* __restrict__ outLo,
    int outOff, int Hs, int Ws) {
    extern __shared__ __align__(16) unsigned short sm[];
    unsigned short* s_w = sm;                    // 3*NT*8*72 u16
    unsigned short* s_h = sm + 3*NT*8*72;        // 324*72 u16
    const int GCNT4 = 3*NT*8*9;                  // uint4 per weight group

    int tid = threadIdx.x;
    int w = tid >> 5, lane = tid & 31, g = lane >> 2, t4 = lane & 3;
    int b = blockIdx.z;
    int x0 = blockIdx.x*16, y0 = blockIdx.y*16;
    unsigned sw_addr = smem_u32(s_w);
    unsigned sh_addr = smem_u32(s_h);

    float acc[2][NT][4];
#pragma unroll
    for (int r = 0; r < 2; r++)
#pragma unroll
        for (int nt = 0; nt < NT; nt++)
#pragma unroll
            for (int q = 0; q < 4; q++) acc[r][nt][q] = 0.f;

    // phases: (halo=Hi,w=Hi), (halo=Hi,w=Lo), (halo=Lo,w=Hi)
#pragma unroll
    for (int ph = 0; ph < 3; ph++) {
        const unsigned* wsrc = (ph == 1) ? wLo : wHi;
        if (ph == 0 || ph == 2) {
            if (ph == 2) __syncthreads();   // prior mma done before halo overwrite
            load_halo(s_h, (ph == 0) ? inHi : inLo, b, x0, y0, Hs, Ws, tid);
        }
        for (int grp = 0; grp < 3; grp++) {
            __syncthreads();                // prev group mma (and halo load) complete
            const uint4* src4 = (const uint4*)(wsrc) + grp*GCNT4;
            uint4* dst4 = (uint4*)s_w;
            for (int i = tid; i < GCNT4; i += 256) dst4[i] = src4[i];
            __syncthreads();
            mma_group<NT>(sw_addr, sh_addr, grp, acc, w, lane);
        }
    }

    if (MODE == 0) {
#pragma unroll
        for (int r = 0; r < 2; r++) {
            int y = y0 + 2*w + r;
            if (y >= Hs) continue;
            size_t rowBase = ((size_t)b*Hs + y)*Ws;
            size_t p0 = (rowBase + x0 + g)*32;
            size_t p1 = (rowBase + x0 + g + 8)*32;
#pragma unroll
            for (int nt = 0; nt < NT; nt++) {
                int c = nt*8 + t4*2;
                float b0v = bias[c], b1v = bias[c+1];
                float v0 = fmaxf(acc[r][nt][0] + b0v, 0.f);
                float v1 = fmaxf(acc[r][nt][1] + b1v, 0.f);
                float v2 = fmaxf(acc[r][nt][2] + b0v, 0.f);
                float v3 = fmaxf(acc[r][nt][3] + b1v, 0.f);
                unsigned short h0,l0,h1,l1,h2,l2,h3,l3;
                bfsplit(v0,h0,l0); bfsplit(v1,h1,l1);
                bfsplit(v2,h2,l2); bfsplit(v3,h3,l3);
                outHi[p0 + nt*4 + t4] = (unsigned)h0 | ((unsigned)h1 << 16);
                outLo[p0 + nt*4 + t4] = (unsigned)l0 | ((unsigned)l1 << 16);
                outHi[p1 + nt*4 + t4] = (unsigned)h2 | ((unsigned)h3 << 16);
                outLo[p1 + nt*4 + t4] = (unsigned)l2 | ((unsigned)l3 << 16);
            }
        }
    } else {
        __syncthreads();
        float* s_d = (float*)s_h;   // 256 px * 33 f32 = 33.8KB <= halo area (46.6KB)
#pragma unroll
        for (int r = 0; r < 2; r++) {
            int pl0 = (2*w + r)*16 + g;
#pragma unroll
            for (int nt = 0; nt < NT; nt++) {
                int c = nt*8 + t4*2;
                s_d[pl0*33 + c]       = acc[r][nt][0];
                s_d[pl0*33 + c + 1]   = acc[r][nt][1];
                s_d[(pl0+8)*33 + c]   = acc[r][nt][2];
                s_d[(pl0+8)*33 + c+1] = acc[r][nt][3];
            }
        }
        __syncthreads();
        int yl = tid / 16, xl = tid % 16;
        int y = y0 + yl;
        if (y >= Hs) return;
        float a[30];
#pragma unroll
        for (int c = 0; c < 30; c++) a[c] = s_d[tid*33 + c] + g_bagc[c];
        size_t pp = (size_t)y*Ws + (x0 + xl);
        size_t Ab = (size_t)b*24*PLANE + outOff + pp;
        size_t Cb = (size_t)b*9*PLANE  + outOff + pp;
#pragma unroll
        for (int k = 0; k < 3; k++) {
            float sab = 1e-6f;
#pragma unroll
            for (int j = 0; j < 8; j++) sab += fabsf(a[k*8+j]);
            float inv = 1.f / sab, sms = 0.f;
#pragma unroll
            for (int j = 0; j < 8; j++) {
                float an = a[k*8+j]*inv;
                g_A[Ab + (size_t)(k*8+j)*PLANE] = an;
                sms += an;
            }
            g_csk[Cb + (size_t)k*PLANE] = 1.f - sms;
        }
        float g0 = a[24], g1 = a[25], g2 = a[26];
        float m = fmaxf(g0, fmaxf(g1, g2));
        float e0 = expf(g0 - m), e1 = expf(g1 - m), e2 = expf(g2 - m);
        float inv = 1.f / (e0 + e1 + e2);
        g_csk[Cb + 3*(size_t)PLANE] = e0*inv;
        g_csk[Cb + 4*(size_t)PLANE] = e1*inv;
        g_csk[Cb + 5*(size_t)PLANE] = e2*inv;
        size_t Vb = (size_t)b*3*PLANE + outOff + pp;
#pragma unroll
        for (int k = 0; k < 3; k++)
            g_curv[Vb + (size_t)k*PLANE] = a[27+k];
    }
}

// ---------------- curv D-part ----------------
__global__ void curvd_kernel(const float* __restrict__ wc, int off, int Hs, int Ws) {
    int NPs = Hs*Ws;
    int gid = blockIdx.x*blockDim.x + threadIdx.x;
    if (gid >= BATCH*NPs) return;
    int b = gid / NPs, p = gid % NPs;
    int y = p / Ws, x = p % Ws;
    const float* Db = g_D + (size_t)b*NPs;
    float dnb[9];
#pragma unroll
    for (int t = 0; t < 9; t++) {
        int dy = t/3 - 1, dx = t%3 - 1;
        int ny = y + dy, nx = x + dx;
        dnb[t] = (ny >= 0 && ny < Hs && nx >= 0 && nx < Ws) ? Db[(size_t)ny*Ws + nx]*0.1f : 0.f;
    }
    size_t Vb = (size_t)b*3*PLANE + off + p;
    size_t Cb = (size_t)b*9*PLANE + off + p;
#pragma unroll
    for (int co = 0; co < 3; co++) {
        float v = g_curv[Vb + (size_t)co*PLANE];
#pragma unroll
        for (int t = 0; t < 9; t++)
            v += wc[((size_t)co*65 + 64)*9 + t] * dnb[t];
        g_csk[Cb + (size_t)(6+co)*PLANE] = 0.1f + 0.9f/(1.f + expf(-v));
    }
}

// ---------------- propagation step ----------------
__global__ void prop_kernel(const float* __restrict__ Din, float* __restrict__ Dout,
                            int off, int Hs, int Ws) {
    int NPs = Hs*Ws;
    int gid = blockIdx.x*blockDim.x + threadIdx.x;
    if (gid >= BATCH*NPs) return;
    int b = gid / NPs, p = gid % NPs;
    int y = p / Ws, x = p % Ws;
    const float* Db = Din + (size_t)b*NPs;
    float d = Db[p];
    size_t Ab = (size_t)b*24*PLANE + off + p;
    size_t Cb = (size_t)b*9*PLANE + off + p;
    const int offy[8] = {-1,-1,-1, 0, 0, 1, 1, 1};
    const int offx[8] = {-1, 0, 1,-1, 1,-1, 0, 1};
    const int dil[3]  = {1, 2, 4};
    float mix = 0.f;
#pragma unroll
    for (int k = 0; k < 3; k++) {
        float agg = g_csk[Cb + (size_t)k*PLANE] * d;
        int dd = dil[k];
#pragma unroll
        for (int j = 0; j < 8; j++) {
            int ny = y + offy[j]*dd, nx = x + offx[j]*dd;
            float nb = (ny >= 0 && ny < Hs && nx >= 0 && nx < Ws) ? Db[(size_t)ny*Ws + nx] : 0.f;
            agg += g_A[Ab + (size_t)(k*8+j)*PLANE] * nb;
        }
        float sig = g_csk[Cb + (size_t)(3+k)*PLANE];
        float kap = g_csk[Cb + (size_t)(6+k)*PLANE];
        mix += sig * (d + kap*(agg - d));
    }
    size_t xb = (size_t)b*6*PLANE + off + p;
    float dls = g_x[xb + 3*(size_t)PLANE];
    float mls = g_x[xb + 4*(size_t)PLANE];
    Dout[(size_t)b*NPs + p] = mls*(0.9f*dls + 0.1f*mix) + (1.f - mls)*mix;
}

// ---------------- host orchestration ----------------
extern "C" void kernel_launch(void* const* d_in, const int* in_sizes, int n_in,
                              void* d_out, int out_size) {
    (void)in_sizes; (void)n_in; (void)out_size;
    const float* I  = (const float*)d_in[0];
    const float* DL = (const float*)d_in[1];
    const float* ML = (const float*)d_in[2];
    const float* E  = (const float*)d_in[3];
    const float* w0 = (const float*)d_in[4];
    const float* b0 = (const float*)d_in[5];
    const float* w1 = (const float*)d_in[6];
    const float* b1 = (const float*)d_in[7];
    const float* w2 = (const float*)d_in[8];
    const float* b2 = (const float*)d_in[9];
    const float* wa = (const float*)d_in[10];
    const float* ba = (const float*)d_in[11];
    const float* wg = (const float*)d_in[12];
    const float* bg = (const float*)d_in[13];
    const float* wc = (const float*)d_in[14];
    const float* bc = (const float*)d_in[15];
    float* out = (float*)d_out;

    float *px, *pD, *pD2, *pDp, *pbagc;
    unsigned *pfh0, *pfl0, *pfh1, *pfl1;
    unsigned *pWh1, *pWl1, *pWh2, *pWl2, *pWha, *pWla;
    cudaGetSymbolAddress((void**)&px,   g_x);
    cudaGetSymbolAddress((void**)&pD,   g_D);
    cudaGetSymbolAddress((void**)&pD2,  g_D2);
    cudaGetSymbolAddress((void**)&pDp,  g_Dp);
    cudaGetSymbolAddress((void**)&pbagc, g_bagc);
    cudaGetSymbolAddress((void**)&pfh0, g_fh0);
    cudaGetSymbolAddress((void**)&pfl0, g_fl0);
    cudaGetSymbolAddress((void**)&pfh1, g_fh1);
    cudaGetSymbolAddress((void**)&pfl1, g_fl1);
    cudaGetSymbolAddress((void**)&pWh1, g_WH1);
    cudaGetSymbolAddress((void**)&pWl1, g_WL1);
    cudaGetSymbolAddress((void**)&pWh2, g_WH2);
    cudaGetSymbolAddress((void**)&pWl2, g_WL2);
    cudaGetSymbolAddress((void**)&pWha, g_WHa);
    cudaGetSymbolAddress((void**)&pWla, g_WLa);

    const int SM_ENC = (3*8*8*72 + 324*72)*2;   // 74,304 B
    const int SM_AGC = (3*4*8*72 + 324*72)*2;   // 60,480 B
    cudaFuncSetAttribute(tconv_mma<8,0>, cudaFuncAttributeMaxDynamicSharedMemorySize, SM_ENC);
    cudaFuncSetAttribute(tconv_mma<4,1>, cudaFuncAttributeMaxDynamicSharedMemorySize, SM_AGC);

    const int SC[3]   = {4, 2, 1};
    const int OFFS[3] = {OFF_S4, OFF_S2, OFF_S1};

    // launch 0: weight prep ; launch 1: s=1 input prep
    prep_weights<<<(95616 + 255)/256, 256>>>(w0, w1, w2, wa, ba, wg, bg, wc, bc);
    {
        int tot = BATCH*H0*W0;
        prep_kernel<1, false><<<(tot+255)/256, 256>>>(I, DL, ML, E, OFF_S1, H0, W0);
    }

    // convs: s=1 first (launch 2 = conv0 scalar, launch 3 = enc1 mma for ncu)
    for (int si = 2; si >= 0; si--) {
        int S = SC[si];
        int off = OFFS[si];
        int Hs = H0/S, Ws = W0/S;
        if (si == 1) {
            int tot = BATCH*Hs*Ws;
            prep_kernel<2, false><<<(tot+255)/256, 256>>>(I, DL, ML, E, OFF_S2, Hs, Ws);
        } else if (si == 0) {
            int tot = BATCH*Hs*Ws;
            prep_kernel<4, true><<<(tot+255)/256, 256>>>(I, DL, ML, E, OFF_S4, Hs, Ws);
        }
        dim3 cb0(CTW, 8);
        dim3 cg0(Ws/CTW, Hs/CTH, BATCH);
        conv0_kernel<<<cg0, cb0>>>(px, PLANE, off, pfh0, pfl0, b0, Hs, Ws);
        dim3 tg(Ws/16, (Hs + 15)/16, BATCH);
        tconv_mma<8,0><<<tg, 256, SM_ENC>>>(pfh0, pfl0, pWh1, pWl1, b1, pfh1, pfl1, 0, Hs, Ws);
        tconv_mma<8,0><<<tg, 256, SM_ENC>>>(pfh1, pfl1, pWh2, pWl2, b2, pfh0, pfl0, 0, Hs, Ws);
        tconv_mma<4,1><<<tg, 256, SM_AGC>>>(pfh0, pfl0, pWha, pWla, pbagc, nullptr, nullptr, off, Hs, Ws);
    }

    // propagation chain: coarse-to-fine
    int Hp = 0, Wp = 0;
    for (int si = 0; si < 3; si++) {
        int S = SC[si];
        int off = OFFS[si];
        int Hs = H0/S, Ws = W0/S, NPs = Hs*Ws;
        int tot = BATCH*NPs, blk = (tot + 255)/256;

        if (si > 0) init_d_kernel<<<blk, 256>>>(off, Hp, Wp, Hs, Ws);
        curvd_kernel<<<blk, 256>>>(wc, off, Hs, Ws);

        float* Dc = pD;
        float* Dn = pD2;
        for (int st = 0; st < 6; st++) {
            prop_kernel<<<blk, 256>>>(Dc, Dn, off, Hs, Ws);
            float* t = Dc; Dc = Dn; Dn = t;
        }
        if (si < 2) {
            cudaMemcpyAsync(pDp, Dc, sizeof(float)*(size_t)BATCH*NPs, cudaMemcpyDeviceToDevice);
        } else {
            cudaMemcpyAsync(out, Dc, sizeof(float)*(size_t)BATCH*NPs, cudaMemcpyDeviceToDevice);
        }
        Hp = Hs; Wp = Ws;
    }
}

// round 17
// speedup vs baseline: 1.6415x; 1.3395x over previous
#include <cuda_runtime.h>
#include <cuda_fp16.h>
#include <math.h>
#include <stdint.h>

#define BATCH 2
#define H0 480
#define W0 640
#define NP0 (H0*W0)

#define PLANE 403200
#define OFF_S4 0
#define OFF_S2 19200
#define OFF_S1 96000

// ---------------- scratch (device globals) ----------------
__device__ float g_x   [BATCH*6 *PLANE];
__device__ float g_A   [BATCH*24*PLANE];
__device__ float g_csk [BATCH*9 *PLANE];
__device__ float g_curv[BATCH*3 *PLANE];
__device__ float g_D   [BATCH*NP0];
__device__ float g_D2  [BATCH*NP0];
__device__ float g_Dp  [BATCH*NP0];

// activations NHWC fp16 pairs: u32 = (fp16 ch c | fp16 ch c+1 << 16), 32 pairs
__device__ __align__(16) unsigned g_f0[BATCH*NP0*32];
__device__ __align__(16) unsigned g_f1[BATCH*NP0*32];

// enc0 scalar weights [ci][tap][co]
__device__ float g_wT0[6*9*64];
// mma weights prepacked [tap][co][ci pad 72] fp16 (hi / lo), 36 u32 per row
__device__ __align__(16) unsigned g_WH1[9*64*36];
__device__ __align__(16) unsigned g_WL1[9*64*36];
__device__ __align__(16) unsigned g_WH2[9*64*36];
__device__ __align__(16) unsigned g_WL2[9*64*36];
__device__ __align__(16) unsigned g_WHa[9*32*36];
__device__ __align__(16) unsigned g_WLa[9*32*36];
__device__ float g_bagc[32];

// ---------------- helpers ----------------
__device__ __forceinline__ uint32_t smem_u32(const void* p) {
    uint32_t a;
    asm("{ .reg .u64 t; cvta.to.shared.u64 t, %1; cvt.u32.u64 %0, t; }" : "=r"(a) : "l"(p));
    return a;
}
__device__ __forceinline__ void fma2(unsigned long long& d, unsigned long long a, unsigned long long b) {
    asm("fma.rn.f32x2 %0, %1, %2, %0;" : "+l"(d) : "l"(a), "l"(b));
}
__device__ __forceinline__ unsigned long long pack2(float lo, float hi) {
    unsigned long long r;
    asm("mov.b64 %0, {%1, %2};" : "=l"(r) : "f"(lo), "f"(hi));
    return r;
}
__device__ __forceinline__ void unpack2(unsigned long long v, float& lo, float& hi) {
    asm("mov.b64 {%0, %1}, %2;" : "=f"(lo), "=f"(hi) : "l"(v));
}
__device__ __forceinline__ void hsplit(float v, unsigned short& h, unsigned short& l) {
    __half hh = __float2half_rn(v);
    float r = v - __half2float(hh);
    __half hl = __float2half_rn(r);
    h = __half_as_ushort(hh);
    l = __half_as_ushort(hl);
}
__device__ __forceinline__ unsigned packh2(float a, float b) {
    __half ha = __float2half_rn(a);
    __half hb = __float2half_rn(b);
    return (unsigned)__half_as_ushort(ha) | ((unsigned)__half_as_ushort(hb) << 16);
}
__device__ __forceinline__ void mma16816(float& c0, float& c1, float& c2, float& c3,
                                         unsigned a0, unsigned a1, unsigned a2, unsigned a3,
                                         unsigned b0, unsigned b1) {
    asm volatile("mma.sync.aligned.m16n8k16.row.col.f32.f16.f16.f32 "
        "{%0,%1,%2,%3}, {%4,%5,%6,%7}, {%8,%9}, {%0,%1,%2,%3};"
        : "+f"(c0), "+f"(c1), "+f"(c2), "+f"(c3)
        : "r"(a0), "r"(a1), "r"(a2), "r"(a3), "r"(b0), "r"(b1));
}
__device__ __forceinline__ void ldsm_x4(unsigned& r0, unsigned& r1, unsigned& r2, unsigned& r3,
                                        unsigned addr) {
    asm volatile("ldmatrix.sync.aligned.m8n8.x4.shared.b16 {%0,%1,%2,%3}, [%4];"
        : "=r"(r0), "=r"(r1), "=r"(r2), "=r"(r3) : "r"(addr));
}

// ---------------- weight prep ----------------
__global__ void prep_weights(const float* __restrict__ w0,
                             const float* __restrict__ w1, const float* __restrict__ w2,
                             const float* __restrict__ wa, const float* __restrict__ ba,
                             const float* __restrict__ wg, const float* __restrict__ bg,
                             const float* __restrict__ wc, const float* __restrict__ bc) {
    int i = blockIdx.x*blockDim.x + threadIdx.x;
    if (i < 32) {
        float bv = 0.f;
        if (i < 24) bv = ba[i];
        else if (i < 27) bv = bg[i-24];
        else if (i < 30) bv = bc[i-27];
        g_bagc[i] = bv;
    }
    if (i < 3456) {                                  // enc0 OIHW -> [ci][t][co]
        int co = i / 54, r = i % 54, ci = r / 9, t = r % 9;
        g_wT0[(ci*9 + t)*64 + co] = w0[i];
    } else if (i < 40320) {                          // enc1: [tap][co][ci72]
        int j = i - 3456;
        int t = j / 4096, rem = j % 4096, co = rem / 64, ci = rem % 64;
        float v = w1[((size_t)co*64 + ci)*9 + t];
        unsigned short h, l; hsplit(v, h, l);
        int idx = (t*64 + co)*72 + ci;
        ((unsigned short*)g_WH1)[idx] = h;
        ((unsigned short*)g_WL1)[idx] = l;
    } else if (i < 77184) {                          // enc2
        int j = i - 40320;
        int t = j / 4096, rem = j % 4096, co = rem / 64, ci = rem % 64;
        float v = w2[((size_t)co*64 + ci)*9 + t];
        unsigned short h, l; hsplit(v, h, l);
        int idx = (t*64 + co)*72 + ci;
        ((unsigned short*)g_WH2)[idx] = h;
        ((unsigned short*)g_WL2)[idx] = l;
    } else if (i < 77184 + 18432) {                  // agc: 32 co
        int j = i - 77184;
        int t = j / 2048, rem = j % 2048, co = rem / 64, ci = rem % 64;
        float v = 0.f;
        if (co < 24)      v = wa[((size_t)co*64 + ci)*9 + t];
        else if (co < 27) v = wg[((size_t)(co-24)*64 + ci)*9 + t];
        else if (co < 30) v = wc[((size_t)(co-27)*65 + ci)*9 + t];
        unsigned short h, l; hsplit(v, h, l);
        int idx = (t*32 + co)*72 + ci;
        ((unsigned short*)g_WHa)[idx] = h;
        ((unsigned short*)g_WLa)[idx] = l;
    }
}

// ---------------- antialiased downsample weights ----------------
template<int F>
__device__ __forceinline__ void down_weights(int i, int n, int& j0, float* w, float& ws) {
    float c = (float)(F*i) + 0.5f*(float)F - 0.5f;
    j0 = (int)ceilf(c - (float)F);
    ws = 0.f;
#pragma unroll
    for (int t = 0; t < 2*F; t++) {
        int j = j0 + t;
        float wv = (j >= 0 && j < n) ? (1.f - fabsf((float)j - c) * (1.f/(float)F)) : 0.f;
        w[t] = wv; ws += wv;
    }
}

// ---------------- per-scale input prep ----------------
template<int S, bool FIRST>
__global__ void prep_kernel(const float* __restrict__ I, const float* __restrict__ DL,
                            const float* __restrict__ ML, const float* __restrict__ E,
                            int off, int Hs, int Ws) {
    int NPs = Hs*Ws;
    int gid = blockIdx.x*blockDim.x + threadIdx.x;
    if (gid >= BATCH*NPs) return;
    int b = gid / NPs, p = gid % NPs;
    int y = p / Ws, x = p % Ws;

    float iv0, iv1, iv2, ev;
    if (S == 1) {
        const float* Ib = I + (size_t)b*3*NP0;
        iv0 = Ib[p]; iv1 = Ib[NP0 + p]; iv2 = Ib[2*NP0 + p];
        ev  = E[(size_t)b*NP0 + p];
    } else {
        float wy[2*S], wx[2*S], wys, wxs;
        int jy0, jx0;
        down_weights<S>(y, H0, jy0, wy, wys);
        down_weights<S>(x, W0, jx0, wx, wxs);
        float a0=0.f, a1=0.f, a2=0.f, ae=0.f;
        const float* Ib = I + (size_t)b*3*NP0;
        const float* Eb = E + (size_t)b*NP0;
#pragma unroll
        for (int ty = 0; ty < 2*S; ty++) {
            int yy = jy0 + ty;
            if (yy < 0 || yy >= H0) continue;
            float wyv = wy[ty];
#pragma unroll
            for (int tx = 0; tx < 2*S; tx++) {
                int xx = jx0 + tx;
                if (xx < 0 || xx >= W0) continue;
                float wv = wyv * wx[tx];
                int q = yy*W0 + xx;
                a0 += wv*Ib[q]; a1 += wv*Ib[NP0 + q]; a2 += wv*Ib[2*NP0 + q]; ae += wv*Eb[q];
            }
        }
        float inv = 1.f / (wys * wxs);
        iv0 = a0*inv; iv1 = a1*inv; iv2 = a2*inv; ev = ae*inv;
    }
    ev = fminf(fmaxf(ev, 0.f), 1.f);

    float dls, mls;
    if (S == 1) {
        mls = ML[(size_t)b*NP0 + p] > 0.f ? 1.f : 0.f;
        dls = DL[(size_t)b*NP0 + p];
    } else {
        float s = 0.f, c = 0.f;
        for (int dy = 0; dy < S; dy++)
            for (int dx = 0; dx < S; dx++) {
                int q = (y*S + dy)*W0 + (x*S + dx);
                float m = ML[(size_t)b*NP0 + q] > 0.f ? 1.f : 0.f;
                c += m;
                s += DL[(size_t)b*NP0 + q] * m;
            }
        mls = c > 0.f ? 1.f : 0.f;
        dls = c > 0.f ? s / (c + 1e-6f) : 0.f;
    }

    size_t xb = (size_t)b*6*PLANE + off;
    g_x[xb + 0*(size_t)PLANE + p] = iv0;
    g_x[xb + 1*(size_t)PLANE + p] = iv1;
    g_x[xb + 2*(size_t)PLANE + p] = iv2;
    g_x[xb + 3*(size_t)PLANE + p] = dls;
    g_x[xb + 4*(size_t)PLANE + p] = mls;
    g_x[xb + 5*(size_t)PLANE + p] = ev;
    if (FIRST) g_D[(size_t)b*NPs + p] = fminf(ev*10.f, 10.f);
}

// ---------------- init D from previous scale ----------------
__global__ void init_d_kernel(int off, int Hp, int Wp, int Hs, int Ws) {
    int NPs = Hs*Ws;
    int gid = blockIdx.x*blockDim.x + threadIdx.x;
    if (gid >= BATCH*NPs) return;
    int b = gid / NPs, p = gid % NPs;
    int y = p / Ws, x = p % Ws;

    const float* Eb = g_x + ((size_t)b*6 + 5)*PLANE + off;
    float e = Eb[p];
    float gxv = (x > 0) ? e - Eb[p-1]  : 0.f;
    float gyv = (y > 0) ? e - Eb[p-Ws] : 0.f;
    float g = fminf(0.5f*(fabsf(gxv)+fabsf(gyv)), 1.f);
    float w = 0.7f * fminf(fmaxf(1.f - g*10.f, 0.f), 1.f);

    float cy = (y + 0.5f)*0.5f - 0.5f;
    float cx = (x + 0.5f)*0.5f - 0.5f;
    int y0 = (int)floorf(cy), x0 = (int)floorf(cx);
    float fy = cy - (float)y0, fx = cx - (float)x0;
    float wyv[2] = {1.f - fy, fy};
    float wxv[2] = {1.f - fx, fx};
    const float* Dpb = g_Dp + (size_t)b*Hp*Wp;
    float wsy = 0.f, wsx = 0.f;
#pragma unroll
    for (int a = 0; a < 2; a++) if (y0+a >= 0 && y0+a < Hp) wsy += wyv[a];
#pragma unroll
    for (int a = 0; a < 2; a++) if (x0+a >= 0 && x0+a < Wp) wsx += wxv[a];
    float acc = 0.f;
#pragma unroll
    for (int a = 0; a < 2; a++) {
        int yy = y0 + a;
        if (yy < 0 || yy >= Hp) continue;
#pragma unroll
        for (int c2 = 0; c2 < 2; c2++) {
            int xx = x0 + c2;
            if (xx < 0 || xx >= Wp) continue;
            acc += wyv[a]*wxv[c2]*Dpb[(size_t)yy*Wp + xx];
        }
    }
    float up = acc / (wsy * wsx);
    float P = fminf(e*10.f, 10.f);
    g_D[(size_t)b*NPs + p] = w*up + (1.f - w)*P;
}

// ---------------- enc0 scalar conv (6->64) -> NHWC fp16 pair planes ----------------
#define CTW 32
#define CTH 8

__global__ void __launch_bounds__(256, 2) conv0_kernel(
    const float* __restrict__ in, int inPS, int inOff,
    unsigned* __restrict__ outA,
    const float* __restrict__ bias, int Hs, int Ws) {
    const int COUT = 64, NCO = 32, Cin = 6;
    __shared__ __align__(16) float s_in[Cin][CTH+2][CTW+2];
    __shared__ __align__(16) float s_w[Cin*9*COUT];

    int b  = blockIdx.z;
    int x0 = blockIdx.x*CTW, y0 = blockIdx.y*CTH;
    int tx = threadIdx.x, ty = threadIdx.y;
    int tid = ty*CTW + tx;
    int r = ty & 3, h = ty >> 2;
    int x = x0 + tx;

    unsigned long long acc[2][NCO/2];
#pragma unroll
    for (int p = 0; p < NCO/2; p++) {
        unsigned long long bv = pack2(bias[h*NCO + 2*p], bias[h*NCO + 2*p + 1]);
        acc[0][p] = bv; acc[1][p] = bv;
    }

    {
        int nW4 = Cin*9*COUT/4;
        const float4* wsrc = (const float4*)g_wT0;
        float4* wdst = (float4*)s_w;
        for (int i = tid; i < nW4; i += 256) wdst[i] = wsrc[i];
        int nI = Cin*(CTH+2)*(CTW+2);
        for (int i = tid; i < nI; i += 256) {
            int c = i / ((CTH+2)*(CTW+2));
            int rr = i % ((CTH+2)*(CTW+2));
            int iy = rr / (CTW+2), ix = rr % (CTW+2);
            int gy = y0 + iy - 1, gx = x0 + ix - 1;
            float v = 0.f;
            if (gy >= 0 && gy < Hs && gx >= 0 && gx < Ws)
                v = in[((size_t)b*6 + c)*inPS + inOff + (size_t)gy*Ws + gx];
            s_in[c][iy][ix] = v;
        }
        __syncthreads();
        for (int ci = 0; ci < Cin; ci++) {
#pragma unroll
            for (int t = 0; t < 9; t++) {
                int dy = t/3, dx = t%3;
                float a0 = s_in[ci][r     + dy][tx + dx];
                float a1 = s_in[ci][r + 4 + dy][tx + dx];
                unsigned long long v0 = pack2(a0, a0);
                unsigned long long v1 = pack2(a1, a1);
                const ulonglong2* wp = (const ulonglong2*)(s_w + (ci*9 + t)*COUT + h*NCO);
#pragma unroll
                for (int q = 0; q < NCO/4; q++) {
                    ulonglong2 wv = wp[q];
                    fma2(acc[0][2*q],   v0, wv.x);
                    fma2(acc[0][2*q+1], v0, wv.y);
                    fma2(acc[1][2*q],   v1, wv.x);
                    fma2(acc[1][2*q+1], v1, wv.y);
                }
            }
        }
    }

#pragma unroll
    for (int i = 0; i < 2; i++) {
        int y = y0 + r + 4*i;
        size_t pixBase = (((size_t)b*Hs + y)*Ws + x)*32;
#pragma unroll
        for (int p = 0; p < NCO/2; p++) {
            float lo, hi;
            unpack2(acc[i][p], lo, hi);
            lo = fmaxf(lo, 0.f); hi = fmaxf(hi, 0.f);
            outA[pixBase + h*16 + p] = packh2(lo, hi);
        }
    }
}

// ---------------- mma conv: 16x16 px tile, 8 warps, fp16 A, split-B, 2 phases ----------------
// smem: s_w [3*NT*8 rows][72 u16], s_h [324 px (18x18)][72 u16].
__device__ __forceinline__ void load_halo(unsigned short* s_h, const unsigned* __restrict__ src,
                                          int b, int x0, int y0, int Hs, int Ws, int tid) {
    for (int i = tid; i < 324*8; i += 256) {
        int px = i >> 3, j4 = i & 7;
        int hy = px / 18, hx = px % 18;
        int gy = y0 + hy - 1, gx = x0 + hx - 1;
        uint4 v = make_uint4(0u, 0u, 0u, 0u);
        if (gy >= 0 && gy < Hs && gx >= 0 && gx < Ws) {
            size_t base = (((size_t)b*Hs + gy)*Ws + gx)*32;
            v = ((const uint4*)(src + base))[j4];
        }
        *(uint4*)(s_h + px*72 + 8*j4) = v;
    }
}

// mma over one 3-tap group (dy = grp, dx = 0..2)
template<int NT>
__device__ __forceinline__ void mma_group(unsigned sw_addr, unsigned sh_addr, int grp,
                                          float (&acc)[2][NT][4], int w, int lane) {
    int m  = lane & 15, kh = lane >> 4;
    int br = lane & 7, bkh = (lane >> 3) & 1, bt = lane >> 4;
    int dy = grp;
#pragma unroll
    for (int dx = 0; dx < 3; dx++) {
#pragma unroll
        for (int kc = 0; kc < 4; kc++) {
            unsigned a[2][4];
#pragma unroll
            for (int r = 0; r < 2; r++) {
                unsigned addr = sh_addr +
                    ((unsigned)(((2*w + r + dy)*18 + m + dx)*72 + kc*16 + kh*8))*2u;
                ldsm_x4(a[r][0], a[r][1], a[r][2], a[r][3], addr);
            }
#pragma unroll
            for (int np = 0; np < NT/2; np++) {
                unsigned b0, b1, b2, b3;
                unsigned baddr = sw_addr +
                    ((unsigned)(((dx*NT + np*2 + bt)*8 + br)*72 + kc*16 + bkh*8))*2u;
                ldsm_x4(b0, b1, b2, b3, baddr);
#pragma unroll
                for (int r = 0; r < 2; r++) {
                    mma16816(acc[r][2*np][0],   acc[r][2*np][1],   acc[r][2*np][2],   acc[r][2*np][3],
                             a[r][0], a[r][1], a[r][2], a[r][3], b0, b1);
                    mma16816(acc[r][2*np+1][0], acc[r][2*np+1][1], acc[r][2*np+1][2], acc[r][2*np+1][3],
                             a[r][0], a[r][1], a[r][2], a[r][3], b2, b3);
                }
            }
        }
    }
}

// MODE 0: relu + NHWC fp16 pair out. MODE 1: fused head epilogue (NT=4).
template<int NT, int MODE>
__global__ void __launch_bounds__(256, 2) tconv_mma(
    const unsigned* __restrict__ inA,
    const unsigned* __restrict__ wHi, const unsigned* __restrict__ wLo,
    const float* __restrict__ bias,
    unsigned* __restrict__ outA,
    int outOff, int Hs, int Ws) {
    extern __shared__ __align__(16) unsigned short sm[];
    unsigned short* s_w = sm;                    // 3*NT*8*72 u16
    unsigned short* s_h = sm + 3*NT*8*72;        // 324*72 u16
    const int GCNT4 = 3*NT*8*9;                  // uint4 per weight group

    int tid = threadIdx.x;
    int w = tid >> 5, lane = tid & 31, g = lane >> 2, t4 = lane & 3;
    int b = blockIdx.z;
    int x0 = blockIdx.x*16, y0 = blockIdx.y*16;
    unsigned sw_addr = smem_u32(s_w);
    unsigned sh_addr = smem_u32(s_h);

    float acc[2][NT][4];
#pragma unroll
    for (int r = 0; r < 2; r++)
#pragma unroll
        for (int nt = 0; nt < NT; nt++)
#pragma unroll
            for (int q = 0; q < 4; q++) acc[r][nt][q] = 0.f;

    load_halo(s_h, inA, b, x0, y0, Hs, Ws, tid);

    // 2 phases: A*Bh, A*Bl
#pragma unroll
    for (int ph = 0; ph < 2; ph++) {
        const unsigned* wsrc = ph ? wLo : wHi;
        for (int grp = 0; grp < 3; grp++) {
            __syncthreads();                // prev group mma (and halo load) complete
            const uint4* src4 = (const uint4*)(wsrc) + grp*GCNT4;
            uint4* dst4 = (uint4*)s_w;
            for (int i = tid; i < GCNT4; i += 256) dst4[i] = src4[i];
            __syncthreads();
            mma_group<NT>(sw_addr, sh_addr, grp, acc, w, lane);
        }
    }

    if (MODE == 0) {
#pragma unroll
        for (int r = 0; r < 2; r++) {
            int y = y0 + 2*w + r;
            if (y >= Hs) continue;
            size_t rowBase = ((size_t)b*Hs + y)*Ws;
            size_t p0 = (rowBase + x0 + g)*32;
            size_t p1 = (rowBase + x0 + g + 8)*32;
#pragma unroll
            for (int nt = 0; nt < NT; nt++) {
                int c = nt*8 + t4*2;
                float b0v = bias[c], b1v = bias[c+1];
                float v0 = fmaxf(acc[r][nt][0] + b0v, 0.f);
                float v1 = fmaxf(acc[r][nt][1] + b1v, 0.f);
                float v2 = fmaxf(acc[r][nt][2] + b0v, 0.f);
                float v3 = fmaxf(acc[r][nt][3] + b1v, 0.f);
                outA[p0 + nt*4 + t4] = packh2(v0, v1);
                outA[p1 + nt*4 + t4] = packh2(v2, v3);
            }
        }
    } else {
        __syncthreads();
        float* s_d = (float*)s_h;   // 256 px * 33 f32 = 33.8KB <= halo area (46.6KB)
#pragma unroll
        for (int r = 0; r < 2; r++) {
            int pl0 = (2*w + r)*16 + g;
#pragma unroll
            for (int nt = 0; nt < NT; nt++) {
                int c = nt*8 + t4*2;
                s_d[pl0*33 + c]       = acc[r][nt][0];
                s_d[pl0*33 + c + 1]   = acc[r][nt][1];
                s_d[(pl0+8)*33 + c]   = acc[r][nt][2];
                s_d[(pl0+8)*33 + c+1] = acc[r][nt][3];
            }
        }
        __syncthreads();
        int yl = tid / 16, xl = tid % 16;
        int y = y0 + yl;
        if (y >= Hs) return;
        float a[30];
#pragma unroll
        for (int c = 0; c < 30; c++) a[c] = s_d[tid*33 + c] + g_bagc[c];
        size_t pp = (size_t)y*Ws + (x0 + xl);
        size_t Ab = (size_t)b*24*PLANE + outOff + pp;
        size_t Cb = (size_t)b*9*PLANE  + outOff + pp;
#pragma unroll
        for (int k = 0; k < 3; k++) {
            float sab = 1e-6f;
#pragma unroll
            for (int j = 0; j < 8; j++) sab += fabsf(a[k*8+j]);
            float inv = 1.f / sab, sms = 0.f;
#pragma unroll
            for (int j = 0; j < 8; j++) {
                float an = a[k*8+j]*inv;
                g_A[Ab + (size_t)(k*8+j)*PLANE] = an;
                sms += an;
            }
            g_csk[Cb + (size_t)k*PLANE] = 1.f - sms;
        }
        float g0 = a[24], g1 = a[25], g2 = a[26];
        float m = fmaxf(g0, fmaxf(g1, g2));
        float e0 = expf(g0 - m), e1 = expf(g1 - m), e2 = expf(g2 - m);
        float inv = 1.f / (e0 + e1 + e2);
        g_csk[Cb + 3*(size_t)PLANE] = e0*inv;
        g_csk[Cb + 4*(size_t)PLANE] = e1*inv;
        g_csk[Cb + 5*(size_t)PLANE] = e2*inv;
        size_t Vb = (size_t)b*3*PLANE + outOff + pp;
#pragma unroll
        for (int k = 0; k < 3; k++)
            g_curv[Vb + (size_t)k*PLANE] = a[27+k];
    }
}

// ---------------- curv D-part ----------------
__global__ void curvd_kernel(const float* __restrict__ wc, int off, int Hs, int Ws) {
    int NPs = Hs*Ws;
    int gid = blockIdx.x*blockDim.x + threadIdx.x;
    if (gid >= BATCH*NPs) return;
    int b = gid / NPs, p = gid % NPs;
    int y = p / Ws, x = p % Ws;
    const float* Db = g_D + (size_t)b*NPs;
    float dnb[9];
#pragma unroll
    for (int t = 0; t < 9; t++) {
        int dy = t/3 - 1, dx = t%3 - 1;
        int ny = y + dy, nx = x + dx;
        dnb[t] = (ny >= 0 && ny < Hs && nx >= 0 && nx < Ws) ? Db[(size_t)ny*Ws + nx]*0.1f : 0.f;
    }
    size_t Vb = (size_t)b*3*PLANE + off + p;
    size_t Cb = (size_t)b*9*PLANE + off + p;
#pragma unroll
    for (int co = 0; co < 3; co++) {
        float v = g_curv[Vb + (size_t)co*PLANE];
#pragma unroll
        for (int t = 0; t < 9; t++)
            v += wc[((size_t)co*65 + 64)*9 + t] * dnb[t];
        g_csk[Cb + (size_t)(6+co)*PLANE] = 0.1f + 0.9f/(1.f + expf(-v));
    }
}

// ---------------- propagation step ----------------
__global__ void prop_kernel(const float* __restrict__ Din, float* __restrict__ Dout,
                            int off, int Hs, int Ws) {
    int NPs = Hs*Ws;
    int gid = blockIdx.x*blockDim.x + threadIdx.x;
    if (gid >= BATCH*NPs) return;
    int b = gid / NPs, p = gid % NPs;
    int y = p / Ws, x = p % Ws;
    const float* Db = Din + (size_t)b*NPs;
    float d = Db[p];
    size_t Ab = (size_t)b*24*PLANE + off + p;
    size_t Cb = (size_t)b*9*PLANE + off + p;
    const int offy[8] = {-1,-1,-1, 0, 0, 1, 1, 1};
    const int offx[8] = {-1, 0, 1,-1, 1,-1, 0, 1};
    const int dil[3]  = {1, 2, 4};
    float mix = 0.f;
#pragma unroll
    for (int k = 0; k < 3; k++) {
        float agg = g_csk[Cb + (size_t)k*PLANE] * d;
        int dd = dil[k];
#pragma unroll
        for (int j = 0; j < 8; j++) {
            int ny = y + offy[j]*dd, nx = x + offx[j]*dd;
            float nb = (ny >= 0 && ny < Hs && nx >= 0 && nx < Ws) ? Db[(size_t)ny*Ws + nx] : 0.f;
            agg += g_A[Ab + (size_t)(k*8+j)*PLANE] * nb;
        }
        float sig = g_csk[Cb + (size_t)(3+k)*PLANE];
        float kap = g_csk[Cb + (size_t)(6+k)*PLANE];
        mix += sig * (d + kap*(agg - d));
    }
    size_t xb = (size_t)b*6*PLANE + off + p;
    float dls = g_x[xb + 3*(size_t)PLANE];
    float mls = g_x[xb + 4*(size_t)PLANE];
    Dout[(size_t)b*NPs + p] = mls*(0.9f*dls + 0.1f*mix) + (1.f - mls)*mix;
}

// ---------------- host orchestration ----------------
extern "C" void kernel_launch(void* const* d_in, const int* in_sizes, int n_in,
                              void* d_out, int out_size) {
    (void)in_sizes; (void)n_in; (void)out_size;
    const float* I  = (const float*)d_in[0];
    const float* DL = (const float*)d_in[1];
    const float* ML = (const float*)d_in[2];
    const float* E  = (const float*)d_in[3];
    const float* w0 = (const float*)d_in[4];
    const float* b0 = (const float*)d_in[5];
    const float* w1 = (const float*)d_in[6];
    const float* b1 = (const float*)d_in[7];
    const float* w2 = (const float*)d_in[8];
    const float* b2 = (const float*)d_in[9];
    const float* wa = (const float*)d_in[10];
    const float* ba = (const float*)d_in[11];
    const float* wg = (const float*)d_in[12];
    const float* bg = (const float*)d_in[13];
    const float* wc = (const float*)d_in[14];
    const float* bc = (const float*)d_in[15];
    float* out = (float*)d_out;

    float *px, *pD, *pD2, *pDp, *pbagc;
    unsigned *pf0, *pf1;
    unsigned *pWh1, *pWl1, *pWh2, *pWl2, *pWha, *pWla;
    cudaGetSymbolAddress((void**)&px,   g_x);
    cudaGetSymbolAddress((void**)&pD,   g_D);
    cudaGetSymbolAddress((void**)&pD2,  g_D2);
    cudaGetSymbolAddress((void**)&pDp,  g_Dp);
    cudaGetSymbolAddress((void**)&pbagc, g_bagc);
    cudaGetSymbolAddress((void**)&pf0,  g_f0);
    cudaGetSymbolAddress((void**)&pf1,  g_f1);
    cudaGetSymbolAddress((void**)&pWh1, g_WH1);
    cudaGetSymbolAddress((void**)&pWl1, g_WL1);
    cudaGetSymbolAddress((void**)&pWh2, g_WH2);
    cudaGetSymbolAddress((void**)&pWl2, g_WL2);
    cudaGetSymbolAddress((void**)&pWha, g_WHa);
    cudaGetSymbolAddress((void**)&pWla, g_WLa);

    const int SM_ENC = (3*8*8*72 + 324*72)*2;   // 74,304 B
    const int SM_AGC = (3*4*8*72 + 324*72)*2;   // 60,480 B
    cudaFuncSetAttribute(tconv_mma<8,0>, cudaFuncAttributeMaxDynamicSharedMemorySize, SM_ENC);
    cudaFuncSetAttribute(tconv_mma<4,1>, cudaFuncAttributeMaxDynamicSharedMemorySize, SM_AGC);

    const int SC[3]   = {4, 2, 1};
    const int OFFS[3] = {OFF_S4, OFF_S2, OFF_S1};

    // launch 0: weight prep ; launch 1: s=1 input prep
    prep_weights<<<(95616 + 255)/256, 256>>>(w0, w1, w2, wa, ba, wg, bg, wc, bc);
    {
        int tot = BATCH*H0*W0;
        prep_kernel<1, false><<<(tot+255)/256, 256>>>(I, DL, ML, E, OFF_S1, H0, W0);
    }

    // convs: s=1 first (launch 2 = conv0 scalar, launch 3 = enc1 mma for ncu)
    for (int si = 2; si >= 0; si--) {
        int S = SC[si];
        int off = OFFS[si];
        int Hs = H0/S, Ws = W0/S;
        if (si == 1) {
            int tot = BATCH*Hs*Ws;
            prep_kernel<2, false><<<(tot+255)/256, 256>>>(I, DL, ML, E, OFF_S2, Hs, Ws);
        } else if (si == 0) {
            int tot = BATCH*Hs*Ws;
            prep_kernel<4, true><<<(tot+255)/256, 256>>>(I, DL, ML, E, OFF_S4, Hs, Ws);
        }
        dim3 cb0(CTW, 8);
        dim3 cg0(Ws/CTW, Hs/CTH, BATCH);
        conv0_kernel<<<cg0, cb0>>>(px, PLANE, off, pf0, b0, Hs, Ws);
        dim3 tg(Ws/16, (Hs + 15)/16, BATCH);
        tconv_mma<8,0><<<tg, 256, SM_ENC>>>(pf0, pWh1, pWl1, b1, pf1, 0, Hs, Ws);
        tconv_mma<8,0><<<tg, 256, SM_ENC>>>(pf1, pWh2, pWl2, b2, pf0, 0, Hs, Ws);
        tconv_mma<4,1><<<tg, 256, SM_AGC>>>(pf0, pWha, pWla, pbagc, nullptr, off, Hs, Ws);
    }

    // propagation chain: coarse-to-fine
    int Hp = 0, Wp = 0;
    for (int si = 0; si < 3; si++) {
        int S = SC[si];
        int off = OFFS[si];
        int Hs = H0/S, Ws = W0/S, NPs = Hs*Ws;
        int tot = BATCH*NPs, blk = (tot + 255)/256;

        if (si > 0) init_d_kernel<<<blk, 256>>>(off, Hp, Wp, Hs, Ws);
        curvd_kernel<<<blk, 256>>>(wc, off, Hs, Ws);

        float* Dc = pD;
        float* Dn = pD2;
        for (int st = 0; st < 6; st++) {
            prop_kernel<<<blk, 256>>>(Dc, Dn, off, Hs, Ws);
            float* t = Dc; Dc = Dn; Dn = t;
        }
        if (si < 2) {
            cudaMemcpyAsync(pDp, Dc, sizeof(float)*(size_t)BATCH*NPs, cudaMemcpyDeviceToDevice);
        } else {
            cudaMemcpyAsync(out, Dc, sizeof(float)*(size_t)BATCH*NPs, cudaMemcpyDeviceToDevice);
        }
        Hp = Hs; Wp = Ws;
    }
}